// round 1
// baseline (speedup 1.0000x reference)
#include <cuda_runtime.h>
#include <math.h>

#define Bb   2
#define Tt   2048
#define Cc   1024
#define Hh   16
#define DHd  64
#define WINw 256
#define Kk   32
#define DFFf 4096
#define Mrows (Bb*Tt)   // 4096

// ---------------- scratch (device globals; no allocs allowed) ----------------
__device__ float g_h   [Mrows*Cc];
__device__ float g_qkv [Mrows*3*Cc];
__device__ float g_ao  [Mrows*Cc];
__device__ float g_proj[Mrows*Cc];
__device__ float g_u   [Mrows*Kk];
__device__ float g_y   [Mrows*Kk];
__device__ float g_tg  [Mrows*Kk];
__device__ float g_trn [Mrows*Cc];
__device__ float g_gate[Mrows];
__device__ float g_x1  [Mrows*Cc];
__device__ float g_f1  [(size_t)Mrows*DFFf];
__device__ float g_f2  [(size_t)Mrows*DFFf];

// ---------------- RMSNorm: one block per row, C=1024 = 256 float4 ----------------
__global__ void rms_kernel(const float* __restrict__ x, const float* __restrict__ w,
                           float* __restrict__ o) {
    int row = blockIdx.x;
    int tid = threadIdx.x;
    const float4* xr = (const float4*)(x + (size_t)row * Cc);
    float4 v = xr[tid];
    float s = v.x*v.x + v.y*v.y + v.z*v.z + v.w*v.w;
    __shared__ float red[8];
    int lane = tid & 31, warp = tid >> 5;
    #pragma unroll
    for (int o2 = 16; o2; o2 >>= 1) s += __shfl_xor_sync(0xffffffffu, s, o2);
    if (lane == 0) red[warp] = s;
    __syncthreads();
    if (warp == 0) {
        float t = (lane < 8) ? red[lane] : 0.f;
        #pragma unroll
        for (int o2 = 4; o2; o2 >>= 1) t += __shfl_xor_sync(0xffffffffu, t, o2);
        if (lane == 0) red[0] = t;
    }
    __syncthreads();
    float inv = rsqrtf(red[0] * (1.0f / Cc) + 1e-6f);
    float4 wv = ((const float4*)w)[tid];
    float4 ov = make_float4(v.x*inv*wv.x, v.y*inv*wv.y, v.z*inv*wv.z, v.w*inv*wv.w);
    ((float4*)(o + (size_t)row * Cc))[tid] = ov;
}

// ---------------- generic SGEMM: C[M,N] = A[M,K] @ W[N,K]^T (+bias / +res) ----------------
// BM=BN=128, BK=8, 256 threads, 8x8 per thread. Dims must divide tiles (they do).
#define BM 128
#define BN 128
#define BK 8
template<int EPI>  // 0 = none, 1 = +bias, 2 = +res
__global__ void sgemm(const float* __restrict__ A, const float* __restrict__ W,
                      const float* __restrict__ bias, const float* __restrict__ res,
                      float* __restrict__ C, int M, int N, int Kd) {
    __shared__ float As[BK][BM];
    __shared__ float Ws[BK][BN];
    int tid = threadIdx.x;
    int bn = blockIdx.x, bm = blockIdx.y;
    int tx = tid & 15, ty = tid >> 4;
    const float* Ap = A + (size_t)bm * BM * Kd;
    const float* Wp = W + (size_t)bn * BN * Kd;
    int lrow = tid >> 1;          // 0..127
    int lcol = (tid & 1) * 4;     // 0 or 4
    float acc[8][8] = {};
    for (int k0 = 0; k0 < Kd; k0 += BK) {
        float4 av = *(const float4*)&Ap[(size_t)lrow * Kd + k0 + lcol];
        float4 wv = *(const float4*)&Wp[(size_t)lrow * Kd + k0 + lcol];
        As[lcol+0][lrow] = av.x; As[lcol+1][lrow] = av.y;
        As[lcol+2][lrow] = av.z; As[lcol+3][lrow] = av.w;
        Ws[lcol+0][lrow] = wv.x; Ws[lcol+1][lrow] = wv.y;
        Ws[lcol+2][lrow] = wv.z; Ws[lcol+3][lrow] = wv.w;
        __syncthreads();
        #pragma unroll
        for (int kk = 0; kk < BK; kk++) {
            float4 a0 = *(const float4*)&As[kk][ty*8];
            float4 a1 = *(const float4*)&As[kk][ty*8+4];
            float4 b0 = *(const float4*)&Ws[kk][tx*8];
            float4 b1 = *(const float4*)&Ws[kk][tx*8+4];
            float ar[8] = {a0.x,a0.y,a0.z,a0.w,a1.x,a1.y,a1.z,a1.w};
            float br[8] = {b0.x,b0.y,b0.z,b0.w,b1.x,b1.y,b1.z,b1.w};
            #pragma unroll
            for (int i = 0; i < 8; i++)
                #pragma unroll
                for (int j = 0; j < 8; j++)
                    acc[i][j] += ar[i] * br[j];
        }
        __syncthreads();
    }
    int crow = bm * BM + ty * 8;
    int ccol = bn * BN + tx * 8;
    #pragma unroll
    for (int i = 0; i < 8; i++) {
        #pragma unroll
        for (int j = 0; j < 8; j++) {
            float v = acc[i][j];
            if (EPI == 1) v += bias[ccol + j];
            if (EPI == 2) v += res[(size_t)(crow + i) * N + ccol + j];
            C[(size_t)(crow + i) * N + ccol + j] = v;
        }
    }
}

// ---------------- windowed causal attention: one CTA per (b,h,q) ----------------
__global__ void attn_kernel(const float* __restrict__ qkv, float* __restrict__ ao) {
    int q = blockIdx.x, h = blockIdx.y, b = blockIdx.z;
    int tid = threadIdx.x;                       // 256 threads
    int lane = tid & 31, warp = tid >> 5;
    __shared__ float qs[DHd];
    __shared__ float sc[WINw];
    __shared__ float red[8];
    __shared__ float sh_m, sh_s;
    __shared__ float avp[4][DHd];

    int kstart = q - (WINw - 1); if (kstart < 0) kstart = 0;
    int nk = q - kstart + 1;

    const float* qptr = qkv + ((size_t)(b * Tt + q) * 3 * Cc) + h * DHd;
    if (tid < DHd) qs[tid] = qptr[tid];
    __syncthreads();

    // scores: one warp per key, lanes over DH (coalesced)
    for (int kk = warp; kk < nk; kk += 8) {
        const float* kp = qkv + ((size_t)(b * Tt + kstart + kk) * 3 * Cc) + Cc + h * DHd;
        float s = qs[lane] * kp[lane] + qs[lane + 32] * kp[lane + 32];
        #pragma unroll
        for (int o2 = 16; o2; o2 >>= 1) s += __shfl_xor_sync(0xffffffffu, s, o2);
        if (lane == 0) sc[kk] = s * 0.125f;     // 1/sqrt(64)
    }
    __syncthreads();

    // softmax max
    float lm = -INFINITY;
    for (int i = tid; i < nk; i += 256) lm = fmaxf(lm, sc[i]);
    #pragma unroll
    for (int o2 = 16; o2; o2 >>= 1) lm = fmaxf(lm, __shfl_xor_sync(0xffffffffu, lm, o2));
    if (lane == 0) red[warp] = lm;
    __syncthreads();
    if (tid == 0) {
        float t = red[0];
        #pragma unroll
        for (int i = 1; i < 8; i++) t = fmaxf(t, red[i]);
        sh_m = t;
    }
    __syncthreads();
    float mx = sh_m;

    // exp + sum
    float ls = 0.f;
    for (int i = tid; i < nk; i += 256) {
        float e = __expf(sc[i] - mx);
        sc[i] = e;
        ls += e;
    }
    #pragma unroll
    for (int o2 = 16; o2; o2 >>= 1) ls += __shfl_xor_sync(0xffffffffu, ls, o2);
    if (lane == 0) red[warp] = ls;
    __syncthreads();
    if (tid == 0) {
        float t = 0.f;
        #pragma unroll
        for (int i = 0; i < 8; i++) t += red[i];
        sh_s = t;
    }
    __syncthreads();
    float inv = 1.0f / sh_s;

    // AV: thread t handles dim d = t&63, key-chunk t>>6 (coalesced V reads)
    int d = tid & 63, chunk = tid >> 6;
    float accv = 0.f;
    for (int kk = chunk; kk < nk; kk += 4) {
        const float* vp = qkv + ((size_t)(b * Tt + kstart + kk) * 3 * Cc) + 2 * Cc + h * DHd;
        accv += sc[kk] * vp[d];
    }
    avp[chunk][d] = accv;
    __syncthreads();
    if (tid < DHd) {
        float ov = (avp[0][tid] + avp[1][tid] + avp[2][tid] + avp[3][tid]) * inv;
        ao[(size_t)(b * Tt + q) * Cc + h * DHd + tid] = ov;
    }
}

// ---------------- skinny GEMM: C[M,32] = A[M,K] @ W[32,K]^T (+bias, opt sigmoid) ----------------
__global__ void gemm_skinny(const float* __restrict__ A, const float* __restrict__ W,
                            const float* __restrict__ bias, float* __restrict__ Cmat,
                            int Kd, int do_sigmoid) {
    __shared__ float As[16][64];
    __shared__ float Ws[32][65];
    int tx = threadIdx.x, ty = threadIdx.y;     // (32, 8)
    int tid = ty * 32 + tx;
    int m0 = blockIdx.x * 16;
    float acc0 = 0.f, acc1 = 0.f;
    for (int k0 = 0; k0 < Kd; k0 += 64) {
        int r = tid >> 4, c4 = (tid & 15) * 4;                 // A: 16x64
        float4 av = *(const float4*)&A[(size_t)(m0 + r) * Kd + k0 + c4];
        *(float4*)&As[r][c4] = av;
        int r2 = tid >> 3, c8 = (tid & 7) * 8;                 // W: 32x64
        float4 w0 = *(const float4*)&W[(size_t)r2 * Kd + k0 + c8];
        float4 w1 = *(const float4*)&W[(size_t)r2 * Kd + k0 + c8 + 4];
        Ws[r2][c8+0]=w0.x; Ws[r2][c8+1]=w0.y; Ws[r2][c8+2]=w0.z; Ws[r2][c8+3]=w0.w;
        Ws[r2][c8+4]=w1.x; Ws[r2][c8+5]=w1.y; Ws[r2][c8+6]=w1.z; Ws[r2][c8+7]=w1.w;
        __syncthreads();
        #pragma unroll
        for (int kk = 0; kk < 64; kk++) {
            float wv = Ws[tx][kk];
            acc0 += As[ty][kk] * wv;
            acc1 += As[ty + 8][kk] * wv;
        }
        __syncthreads();
    }
    float b0 = bias ? bias[tx] : 0.f;
    float v0 = acc0 + b0, v1 = acc1 + b0;
    if (do_sigmoid) {
        v0 = 1.f / (1.f + __expf(-v0));
        v1 = 1.f / (1.f + __expf(-v1));
    }
    Cmat[(size_t)(m0 + ty) * Kk + tx]     = v0;
    Cmat[(size_t)(m0 + ty + 8) * Kk + tx] = v1;
}

// ---------------- oscillator scan: 64 independent (b,k) chains ----------------
__global__ void scan_kernel(const float* __restrict__ u, const float* __restrict__ a_logit,
                            const float* __restrict__ theta, float* __restrict__ y) {
    int idx = threadIdx.x;                   // 64 threads
    int b = idx / Kk, k = idx % Kk;
    float a  = 1.f / (1.f + expf(-a_logit[k]));
    float ct = cosf(theta[k]), st = sinf(theta[k]);
    float sr = 0.f, si = 0.f;
    const float* up = u + (size_t)b * Tt * Kk + k;
    float*       yp = y + (size_t)b * Tt * Kk + k;
    for (int t = 0; t < Tt; t++) {
        float ut = up[(size_t)t * Kk];
        float nsr = a * (ct * sr - st * si) + ut;
        float nsi = a * (st * sr + ct * si);
        sr = nsr; si = nsi;
        yp[(size_t)t * Kk] = sr;
    }
}

// ---------------- trn_out = ((tg*y) @ Wout^T) * scale ----------------
__global__ void trn_out_kernel(const float* __restrict__ tg, const float* __restrict__ y,
                               const float* __restrict__ wout, const float* __restrict__ scale_p,
                               float* __restrict__ out) {
    __shared__ float Zs[16][33];
    __shared__ float Ws[64][33];
    int tx = threadIdx.x, ty = threadIdx.y;   // (64, 4)
    int tid = ty * 64 + tx;
    int m0 = blockIdx.x * 16, c0 = blockIdx.y * 64;
    for (int i = tid; i < 16 * Kk; i += 256) {
        int r = i >> 5, k = i & 31;
        size_t off = (size_t)(m0 + r) * Kk + k;
        Zs[r][k] = tg[off] * y[off];
    }
    for (int i = tid; i < 64 * Kk; i += 256) {
        int r = i >> 5, k = i & 31;
        Ws[r][k] = wout[(size_t)(c0 + r) * Kk + k];
    }
    __syncthreads();
    float scale = scale_p[0];
    float acc[4] = {0.f, 0.f, 0.f, 0.f};
    #pragma unroll
    for (int k = 0; k < Kk; k++) {
        float wv = Ws[tx][k];
        acc[0] += Zs[ty][k]      * wv;
        acc[1] += Zs[ty + 4][k]  * wv;
        acc[2] += Zs[ty + 8][k]  * wv;
        acc[3] += Zs[ty + 12][k] * wv;
    }
    #pragma unroll
    for (int r = 0; r < 4; r++)
        out[(size_t)(m0 + ty + 4 * r) * Cc + c0 + tx] = acc[r] * scale;
}

// ---------------- scalar gate: g = sigmoid(h . gate_w + gate_b), per row ----------------
__global__ void gate_kernel(const float* __restrict__ h, const float* __restrict__ gw,
                            const float* __restrict__ gb, float* __restrict__ g) {
    int row = blockIdx.x, tid = threadIdx.x;
    float4 a = ((const float4*)(h + (size_t)row * Cc))[tid];
    float4 w = ((const float4*)gw)[tid];
    float s = a.x*w.x + a.y*w.y + a.z*w.z + a.w*w.w;
    __shared__ float red[8];
    int lane = tid & 31, warp = tid >> 5;
    #pragma unroll
    for (int o2 = 16; o2; o2 >>= 1) s += __shfl_xor_sync(0xffffffffu, s, o2);
    if (lane == 0) red[warp] = s;
    __syncthreads();
    if (tid == 0) {
        float t = 0.f;
        #pragma unroll
        for (int i = 0; i < 8; i++) t += red[i];
        g[row] = 1.f / (1.f + __expf(-(t + gb[0])));
    }
}

// ---------------- mix: x1 = x + g*ao_proj + (1-g)*trn ----------------
__global__ void mix_kernel(const float* __restrict__ x, const float* __restrict__ ap,
                           const float* __restrict__ trn, const float* __restrict__ g,
                           float* __restrict__ o) {
    int idx = blockIdx.x * blockDim.x + threadIdx.x;   // float4 index
    if (idx >= Mrows * Cc / 4) return;
    float gg = g[idx / (Cc / 4)];
    float og = 1.f - gg;
    float4 xv = ((const float4*)x)[idx];
    float4 av = ((const float4*)ap)[idx];
    float4 tv = ((const float4*)trn)[idx];
    float4 ov = make_float4(xv.x + gg*av.x + og*tv.x,
                            xv.y + gg*av.y + og*tv.y,
                            xv.z + gg*av.z + og*tv.z,
                            xv.w + gg*av.w + og*tv.w);
    ((float4*)o)[idx] = ov;
}

// ---------------- silu(f1)*f2 -> f1 ----------------
__global__ void silumul_kernel(float* __restrict__ f1, const float* __restrict__ f2, int n4) {
    int idx = blockIdx.x * blockDim.x + threadIdx.x;
    if (idx >= n4) return;
    float4 a = ((const float4*)f1)[idx];
    float4 b = ((const float4*)f2)[idx];
    float4 o;
    o.x = a.x / (1.f + __expf(-a.x)) * b.x;
    o.y = a.y / (1.f + __expf(-a.y)) * b.y;
    o.z = a.z / (1.f + __expf(-a.z)) * b.z;
    o.w = a.w / (1.f + __expf(-a.w)) * b.w;
    ((float4*)f1)[idx] = o;
}

// ---------------- launch ----------------
extern "C" void kernel_launch(void* const* d_in, const int* in_sizes, int n_in,
                              void* d_out, int out_size) {
    const float* x          = (const float*)d_in[0];
    const float* norm1_w    = (const float*)d_in[1];
    const float* qkv_w      = (const float*)d_in[2];
    const float* qkv_b      = (const float*)d_in[3];
    const float* proj_w     = (const float*)d_in[4];
    const float* proj_b     = (const float*)d_in[5];
    const float* gate_w     = (const float*)d_in[6];
    const float* gate_b     = (const float*)d_in[7];
    const float* trn_win    = (const float*)d_in[8];
    const float* trn_wout   = (const float*)d_in[9];
    const float* trn_gate_w = (const float*)d_in[10];
    const float* trn_gate_b = (const float*)d_in[11];
    const float* trn_a      = (const float*)d_in[12];
    const float* trn_theta  = (const float*)d_in[13];
    const float* trn_scale  = (const float*)d_in[14];
    const float* norm2_w    = (const float*)d_in[15];
    const float* ffn_gate_w = (const float*)d_in[16];
    const float* ffn_up_w   = (const float*)d_in[17];
    const float* ffn_down_w = (const float*)d_in[18];
    float* out = (float*)d_out;

    float *h, *qkv, *ao, *proj, *u, *y, *tg, *trn, *gate, *x1, *f1, *f2;
    cudaGetSymbolAddress((void**)&h,    g_h);
    cudaGetSymbolAddress((void**)&qkv,  g_qkv);
    cudaGetSymbolAddress((void**)&ao,   g_ao);
    cudaGetSymbolAddress((void**)&proj, g_proj);
    cudaGetSymbolAddress((void**)&u,    g_u);
    cudaGetSymbolAddress((void**)&y,    g_y);
    cudaGetSymbolAddress((void**)&tg,   g_tg);
    cudaGetSymbolAddress((void**)&trn,  g_trn);
    cudaGetSymbolAddress((void**)&gate, g_gate);
    cudaGetSymbolAddress((void**)&x1,   g_x1);
    cudaGetSymbolAddress((void**)&f1,   g_f1);
    cudaGetSymbolAddress((void**)&f2,   g_f2);

    // 1) h = rms(x, norm1_w)
    rms_kernel<<<Mrows, 256>>>(x, norm1_w, h);
    // 2) qkv = h @ qkv_w^T + qkv_b
    sgemm<1><<<dim3(3 * Cc / BN, Mrows / BM), 256>>>(h, qkv_w, qkv_b, nullptr, qkv, Mrows, 3 * Cc, Cc);
    // 3) attention
    attn_kernel<<<dim3(Tt, Hh, Bb), 256>>>(qkv, ao);
    // 4) proj
    sgemm<1><<<dim3(Cc / BN, Mrows / BM), 256>>>(ao, proj_w, proj_b, nullptr, proj, Mrows, Cc, Cc);
    // 5) TRN branch
    gemm_skinny<<<Mrows / 16, dim3(32, 8)>>>(h, trn_win, nullptr, u, Cc, 0);
    gemm_skinny<<<Mrows / 16, dim3(32, 8)>>>(h, trn_gate_w, trn_gate_b, tg, Cc, 1);
    scan_kernel<<<1, Bb * Kk>>>(u, trn_a, trn_theta, y);
    trn_out_kernel<<<dim3(Mrows / 16, Cc / 64), dim3(64, 4)>>>(tg, y, trn_wout, trn_scale, trn);
    // 6) gate + mix
    gate_kernel<<<Mrows, 256>>>(h, gate_w, gate_b, gate);
    mix_kernel<<<(Mrows * Cc / 4 + 255) / 256, 256>>>(x, proj, trn, gate, x1);
    // 7) FFN
    rms_kernel<<<Mrows, 256>>>(x1, norm2_w, h);
    sgemm<0><<<dim3(DFFf / BN, Mrows / BM), 256>>>(h, ffn_gate_w, nullptr, nullptr, f1, Mrows, DFFf, Cc);
    sgemm<0><<<dim3(DFFf / BN, Mrows / BM), 256>>>(h, ffn_up_w, nullptr, nullptr, f2, Mrows, DFFf, Cc);
    silumul_kernel<<<((int)((size_t)Mrows * DFFf / 4) + 255) / 256, 256>>>(f1, f2, Mrows * (DFFf / 4));
    // 8) out = f1 @ ffn_down_w^T + x1
    sgemm<2><<<dim3(Cc / BN, Mrows / BM), 256>>>(f1, ffn_down_w, nullptr, x1, out, Mrows, Cc, DFFf);
}

// round 2
// speedup vs baseline: 1.1967x; 1.1967x over previous
#include <cuda_runtime.h>
#include <math.h>

#define Bb   2
#define Tt   2048
#define Cc   1024
#define Hh   16
#define DHd  64
#define WINw 256
#define Kk   32
#define DFFf 4096
#define Mrows (Bb*Tt)   // 4096

// ---------------- scratch (device globals; no allocs allowed) ----------------
__device__ float g_h   [Mrows*Cc];
__device__ float g_qkv [Mrows*3*Cc];
__device__ float g_ao  [Mrows*Cc];
__device__ float g_proj[Mrows*Cc];
__device__ float g_u   [Mrows*Kk];
__device__ float g_y   [Mrows*Kk];
__device__ float g_tg  [Mrows*Kk];
__device__ float g_trn [Mrows*Cc];
__device__ float g_gate[Mrows];
__device__ float g_x1  [Mrows*Cc];
__device__ float g_f1  [(size_t)Mrows*DFFf];
__device__ float g_f2  [(size_t)Mrows*DFFf];

// ---------------- RMSNorm ----------------
__global__ void rms_kernel(const float* __restrict__ x, const float* __restrict__ w,
                           float* __restrict__ o) {
    int row = blockIdx.x;
    int tid = threadIdx.x;
    const float4* xr = (const float4*)(x + (size_t)row * Cc);
    float4 v = xr[tid];
    float s = v.x*v.x + v.y*v.y + v.z*v.z + v.w*v.w;
    __shared__ float red[8];
    int lane = tid & 31, warp = tid >> 5;
    #pragma unroll
    for (int o2 = 16; o2; o2 >>= 1) s += __shfl_xor_sync(0xffffffffu, s, o2);
    if (lane == 0) red[warp] = s;
    __syncthreads();
    if (warp == 0) {
        float t = (lane < 8) ? red[lane] : 0.f;
        #pragma unroll
        for (int o2 = 4; o2; o2 >>= 1) t += __shfl_xor_sync(0xffffffffu, t, o2);
        if (lane == 0) red[0] = t;
    }
    __syncthreads();
    float inv = rsqrtf(red[0] * (1.0f / Cc) + 1e-6f);
    float4 wv = ((const float4*)w)[tid];
    float4 ov = make_float4(v.x*inv*wv.x, v.y*inv*wv.y, v.z*inv*wv.z, v.w*inv*wv.w);
    ((float4*)(o + (size_t)row * Cc))[tid] = ov;
}

// ---------------- double-buffered SGEMM: C[M,N] = A[M,K] @ W[N,K]^T ----------------
#define BM 128
#define BN 128
#define BK 8
template<int EPI>  // 0 = none, 1 = +bias, 2 = +res
__global__ void __launch_bounds__(256, 2)
sgemm(const float* __restrict__ A, const float* __restrict__ W,
      const float* __restrict__ bias, const float* __restrict__ res,
      float* __restrict__ C, int M, int N, int Kd) {
    __shared__ float As[2][BK][BM];
    __shared__ float Ws[2][BK][BN];
    int tid = threadIdx.x;
    int bn = blockIdx.x, bm = blockIdx.y;
    int tx = tid & 15, ty = tid >> 4;
    const float* Ap = A + (size_t)bm * BM * Kd;
    const float* Wp = W + (size_t)bn * BN * Kd;
    int lrow = tid >> 1;          // 0..127
    int lcol = (tid & 1) * 4;     // 0 or 4

    // first tile
    {
        float4 av = *(const float4*)&Ap[(size_t)lrow * Kd + lcol];
        float4 wv = *(const float4*)&Wp[(size_t)lrow * Kd + lcol];
        As[0][lcol+0][lrow] = av.x; As[0][lcol+1][lrow] = av.y;
        As[0][lcol+2][lrow] = av.z; As[0][lcol+3][lrow] = av.w;
        Ws[0][lcol+0][lrow] = wv.x; Ws[0][lcol+1][lrow] = wv.y;
        Ws[0][lcol+2][lrow] = wv.z; Ws[0][lcol+3][lrow] = wv.w;
    }
    __syncthreads();

    float acc[8][8] = {};
    int cur = 0;
    for (int k0 = 0; k0 < Kd; k0 += BK) {
        bool more = (k0 + BK) < Kd;
        float4 na, nw;
        if (more) {
            na = *(const float4*)&Ap[(size_t)lrow * Kd + k0 + BK + lcol];
            nw = *(const float4*)&Wp[(size_t)lrow * Kd + k0 + BK + lcol];
        }
        #pragma unroll
        for (int kk = 0; kk < BK; kk++) {
            float4 a0 = *(const float4*)&As[cur][kk][ty*8];
            float4 a1 = *(const float4*)&As[cur][kk][ty*8+4];
            float4 b0 = *(const float4*)&Ws[cur][kk][tx*8];
            float4 b1 = *(const float4*)&Ws[cur][kk][tx*8+4];
            float ar[8] = {a0.x,a0.y,a0.z,a0.w,a1.x,a1.y,a1.z,a1.w};
            float br[8] = {b0.x,b0.y,b0.z,b0.w,b1.x,b1.y,b1.z,b1.w};
            #pragma unroll
            for (int i = 0; i < 8; i++)
                #pragma unroll
                for (int j = 0; j < 8; j++)
                    acc[i][j] += ar[i] * br[j];
        }
        if (more) {
            int nxt = cur ^ 1;
            As[nxt][lcol+0][lrow] = na.x; As[nxt][lcol+1][lrow] = na.y;
            As[nxt][lcol+2][lrow] = na.z; As[nxt][lcol+3][lrow] = na.w;
            Ws[nxt][lcol+0][lrow] = nw.x; Ws[nxt][lcol+1][lrow] = nw.y;
            Ws[nxt][lcol+2][lrow] = nw.z; Ws[nxt][lcol+3][lrow] = nw.w;
            __syncthreads();
            cur = nxt;
        }
    }
    int crow = bm * BM + ty * 8;
    int ccol = bn * BN + tx * 8;
    #pragma unroll
    for (int i = 0; i < 8; i++) {
        #pragma unroll
        for (int j = 0; j < 8; j++) {
            float v = acc[i][j];
            if (EPI == 1) v += bias[ccol + j];
            if (EPI == 2) v += res[(size_t)(crow + i) * N + ccol + j];
            C[(size_t)(crow + i) * N + ccol + j] = v;
        }
    }
}

// ---------------- tiled windowed attention: one CTA per (b,h, 64-query tile) ----------------
// keys span j in [0,384), kg = q0-256+j ; valid iff j in [qi+1, qi+256] && kg>=0
#define QT 64
#define NJ 384
#define PSL 388   // padded row length for Ps
#define ATTN_SMEM ((64*68*2 + 64*PSL + 64) * 4)

__global__ void attn_tiled(const float* __restrict__ qkv, float* __restrict__ ao) {
    extern __shared__ float sm[];
    float* Qs   = sm;                 // 64 x 68
    float* KVs  = Qs + 64*68;         // 64 x 68
    float* Ps   = KVs + 64*68;        // 64 x PSL
    float* rsum = Ps + 64*PSL;        // 64

    int q0 = blockIdx.x * QT;
    int h = blockIdx.y, b = blockIdx.z;
    int tid = threadIdx.x;            // 256
    const size_t rs = 3 * Cc;
    const float* qbase = qkv + (size_t)b * Tt * rs + h * DHd;

    // load Q tile
    for (int i = tid; i < 64*16; i += 256) {
        int r = i >> 4, c4 = (i & 15) * 4;
        *(float4*)&Qs[r*68 + c4] =
            *(const float4*)(qbase + (size_t)(q0 + r) * rs + c4);
    }
    int kbase = q0 - 256;
    int tx = tid & 15, ty = tid >> 4;

    // ---- phase 1: scores ----
    for (int cc = 0; cc < 6; cc++) {
        for (int i = tid; i < 64*16; i += 256) {
            int r = i >> 4, c4 = (i & 15) * 4;
            int kg = kbase + cc*64 + r;
            float4 v = make_float4(0.f, 0.f, 0.f, 0.f);
            if (kg >= 0 && kg < Tt)
                v = *(const float4*)(qbase + Cc + (size_t)kg * rs + c4);
            *(float4*)&KVs[r*68 + c4] = v;
        }
        __syncthreads();

        float acc[4][4] = {};
        #pragma unroll 4
        for (int d = 0; d < 64; d += 4) {
            float4 qv[4], kv[4];
            #pragma unroll
            for (int r = 0; r < 4; r++) qv[r] = *(float4*)&Qs[(ty*4+r)*68 + d];
            #pragma unroll
            for (int c = 0; c < 4; c++) kv[c] = *(float4*)&KVs[(tx*4+c)*68 + d];
            #pragma unroll
            for (int r = 0; r < 4; r++)
                #pragma unroll
                for (int c = 0; c < 4; c++)
                    acc[r][c] += qv[r].x*kv[c].x + qv[r].y*kv[c].y
                               + qv[r].z*kv[c].z + qv[r].w*kv[c].w;
        }
        #pragma unroll
        for (int r = 0; r < 4; r++) {
            int qi = ty*4 + r;
            #pragma unroll
            for (int c = 0; c < 4; c++) {
                int j = cc*64 + tx*4 + c;
                int kg = kbase + j;
                bool valid = (j >= qi + 1) && (j <= qi + 256) && (kg >= 0);
                Ps[qi*PSL + j] = valid ? acc[r][c] * 0.125f : -1e30f;
            }
        }
        __syncthreads();
    }

    // ---- phase 2: softmax (warp per row group) ----
    int lane = tid & 31, wrp = tid >> 5;
    for (int q = wrp; q < 64; q += 8) {
        float m = -INFINITY;
        for (int j = lane; j < NJ; j += 32) m = fmaxf(m, Ps[q*PSL + j]);
        #pragma unroll
        for (int o2 = 16; o2; o2 >>= 1) m = fmaxf(m, __shfl_xor_sync(0xffffffffu, m, o2));
        float s = 0.f;
        for (int j = lane; j < NJ; j += 32) {
            float e = __expf(Ps[q*PSL + j] - m);
            Ps[q*PSL + j] = e;
            s += e;
        }
        #pragma unroll
        for (int o2 = 16; o2; o2 >>= 1) s += __shfl_xor_sync(0xffffffffu, s, o2);
        if (lane == 0) rsum[q] = 1.0f / s;
    }
    __syncthreads();

    // ---- phase 3: AV ----
    float4 o0 = make_float4(0,0,0,0), o1 = o0, o2v = o0, o3 = o0;
    for (int cc = 0; cc < 6; cc++) {
        for (int i = tid; i < 64*16; i += 256) {
            int r = i >> 4, c4 = (i & 15) * 4;
            int kg = kbase + cc*64 + r;
            float4 v = make_float4(0.f, 0.f, 0.f, 0.f);
            if (kg >= 0 && kg < Tt)
                v = *(const float4*)(qbase + 2*Cc + (size_t)kg * rs + c4);
            *(float4*)&KVs[r*68 + c4] = v;
        }
        __syncthreads();
        #pragma unroll 4
        for (int jj = 0; jj < 64; jj++) {
            int j = cc*64 + jj;
            float4 vv = *(float4*)&KVs[jj*68 + tx*4];
            float p0 = Ps[(ty*4+0)*PSL + j];
            float p1 = Ps[(ty*4+1)*PSL + j];
            float p2 = Ps[(ty*4+2)*PSL + j];
            float p3 = Ps[(ty*4+3)*PSL + j];
            o0.x += p0*vv.x; o0.y += p0*vv.y; o0.z += p0*vv.z; o0.w += p0*vv.w;
            o1.x += p1*vv.x; o1.y += p1*vv.y; o1.z += p1*vv.z; o1.w += p1*vv.w;
            o2v.x += p2*vv.x; o2v.y += p2*vv.y; o2v.z += p2*vv.z; o2v.w += p2*vv.w;
            o3.x += p3*vv.x; o3.y += p3*vv.y; o3.z += p3*vv.z; o3.w += p3*vv.w;
        }
        __syncthreads();
    }
    {
        float4 outs[4] = {o0, o1, o2v, o3};
        #pragma unroll
        for (int r = 0; r < 4; r++) {
            int q = ty*4 + r;
            float inv = rsum[q];
            float4 ov = outs[r];
            ov.x *= inv; ov.y *= inv; ov.z *= inv; ov.w *= inv;
            *(float4*)(ao + (size_t)(b*Tt + q0 + q)*Cc + h*DHd + tx*4) = ov;
        }
    }
}

// ---------------- skinny GEMM: C[M,32] = A[M,K] @ W[32,K]^T ----------------
__global__ void gemm_skinny(const float* __restrict__ A, const float* __restrict__ W,
                            const float* __restrict__ bias, float* __restrict__ Cmat,
                            int Kd, int do_sigmoid) {
    __shared__ float As[16][64];
    __shared__ float Ws[32][65];
    int tx = threadIdx.x, ty = threadIdx.y;     // (32, 8)
    int tid = ty * 32 + tx;
    int m0 = blockIdx.x * 16;
    float acc0 = 0.f, acc1 = 0.f;
    for (int k0 = 0; k0 < Kd; k0 += 64) {
        int r = tid >> 4, c4 = (tid & 15) * 4;
        float4 av = *(const float4*)&A[(size_t)(m0 + r) * Kd + k0 + c4];
        *(float4*)&As[r][c4] = av;
        int r2 = tid >> 3, c8 = (tid & 7) * 8;
        float4 w0 = *(const float4*)&W[(size_t)r2 * Kd + k0 + c8];
        float4 w1 = *(const float4*)&W[(size_t)r2 * Kd + k0 + c8 + 4];
        Ws[r2][c8+0]=w0.x; Ws[r2][c8+1]=w0.y; Ws[r2][c8+2]=w0.z; Ws[r2][c8+3]=w0.w;
        Ws[r2][c8+4]=w1.x; Ws[r2][c8+5]=w1.y; Ws[r2][c8+6]=w1.z; Ws[r2][c8+7]=w1.w;
        __syncthreads();
        #pragma unroll
        for (int kk = 0; kk < 64; kk++) {
            float wv = Ws[tx][kk];
            acc0 += As[ty][kk] * wv;
            acc1 += As[ty + 8][kk] * wv;
        }
        __syncthreads();
    }
    float b0 = bias ? bias[tx] : 0.f;
    float v0 = acc0 + b0, v1 = acc1 + b0;
    if (do_sigmoid) {
        v0 = 1.f / (1.f + __expf(-v0));
        v1 = 1.f / (1.f + __expf(-v1));
    }
    Cmat[(size_t)(m0 + ty) * Kk + tx]     = v0;
    Cmat[(size_t)(m0 + ty + 8) * Kk + tx] = v1;
}

// ---------------- chunked parallel oscillator scan ----------------
// S_end(chunk) = M^64 * S_start + L ; M^64 = a^64 * R(64*theta) closed-form.
__global__ void scan_kernel(const float* __restrict__ u, const float* __restrict__ a_logit,
                            const float* __restrict__ theta, float* __restrict__ y) {
    __shared__ float ssr[32][33], ssi[32][33];   // [chunk][k]
    int b = blockIdx.x;
    int tid = threadIdx.x;                       // 1024
    int k = tid & 31, c = tid >> 5;              // 32 chunks of 64 steps
    float a  = 1.f / (1.f + __expf(-a_logit[k]));
    float ct = cosf(theta[k]), st = sinf(theta[k]);
    const float* up = u + (size_t)b * Tt * Kk + k;
    int t0 = c * 64;

    // pass A: local chunk state from zero init
    float sr = 0.f, si = 0.f;
    for (int i = 0; i < 64; i++) {
        float ut = up[(size_t)(t0 + i) * Kk];
        float nsr = a * (ct * sr - st * si) + ut;
        float nsi = a * (st * sr + ct * si);
        sr = nsr; si = nsi;
    }
    ssr[c][k] = sr; ssi[c][k] = si;
    __syncthreads();

    // pass B: serial combine over chunks (one thread per k)
    if (tid < 32) {
        int kq = tid;
        float aq = 1.f / (1.f + __expf(-a_logit[kq]));
        float a64 = __powf(aq, 64.f);
        float th = theta[kq];
        float c64 = cosf(64.f * th), s64 = sinf(64.f * th);
        float M00 = a64 * c64, M01 = -a64 * s64;
        float M10 = a64 * s64, M11 =  a64 * c64;
        float cr = 0.f, ci = 0.f;
        for (int cc = 0; cc < 32; cc++) {
            float lr = ssr[cc][kq], li = ssi[cc][kq];
            ssr[cc][kq] = cr; ssi[cc][kq] = ci;   // true init for chunk cc
            float nr = M00 * cr + M01 * ci + lr;
            float ni = M10 * cr + M11 * ci + li;
            cr = nr; ci = ni;
        }
    }
    __syncthreads();

    // pass C: replay with correct init, write y
    sr = ssr[c][k]; si = ssi[c][k];
    float* yp = y + (size_t)b * Tt * Kk + k;
    for (int i = 0; i < 64; i++) {
        float ut = up[(size_t)(t0 + i) * Kk];
        float nsr = a * (ct * sr - st * si) + ut;
        float nsi = a * (st * sr + ct * si);
        sr = nsr; si = nsi;
        yp[(size_t)(t0 + i) * Kk] = sr;
    }
}

// ---------------- trn_out = ((tg*y) @ Wout^T) * scale ----------------
__global__ void trn_out_kernel(const float* __restrict__ tg, const float* __restrict__ y,
                               const float* __restrict__ wout, const float* __restrict__ scale_p,
                               float* __restrict__ out) {
    __shared__ float Zs[16][33];
    __shared__ float Ws[64][33];
    int tx = threadIdx.x, ty = threadIdx.y;   // (64, 4)
    int tid = ty * 64 + tx;
    int m0 = blockIdx.x * 16, c0 = blockIdx.y * 64;
    for (int i = tid; i < 16 * Kk; i += 256) {
        int r = i >> 5, k = i & 31;
        size_t off = (size_t)(m0 + r) * Kk + k;
        Zs[r][k] = tg[off] * y[off];
    }
    for (int i = tid; i < 64 * Kk; i += 256) {
        int r = i >> 5, k = i & 31;
        Ws[r][k] = wout[(size_t)(c0 + r) * Kk + k];
    }
    __syncthreads();
    float scale = scale_p[0];
    float acc[4] = {0.f, 0.f, 0.f, 0.f};
    #pragma unroll
    for (int k = 0; k < Kk; k++) {
        float wv = Ws[tx][k];
        acc[0] += Zs[ty][k]      * wv;
        acc[1] += Zs[ty + 4][k]  * wv;
        acc[2] += Zs[ty + 8][k]  * wv;
        acc[3] += Zs[ty + 12][k] * wv;
    }
    #pragma unroll
    for (int r = 0; r < 4; r++)
        out[(size_t)(m0 + ty + 4 * r) * Cc + c0 + tx] = acc[r] * scale;
}

// ---------------- scalar gate ----------------
__global__ void gate_kernel(const float* __restrict__ h, const float* __restrict__ gw,
                            const float* __restrict__ gb, float* __restrict__ g) {
    int row = blockIdx.x, tid = threadIdx.x;
    float4 a = ((const float4*)(h + (size_t)row * Cc))[tid];
    float4 w = ((const float4*)gw)[tid];
    float s = a.x*w.x + a.y*w.y + a.z*w.z + a.w*w.w;
    __shared__ float red[8];
    int lane = tid & 31, warp = tid >> 5;
    #pragma unroll
    for (int o2 = 16; o2; o2 >>= 1) s += __shfl_xor_sync(0xffffffffu, s, o2);
    if (lane == 0) red[warp] = s;
    __syncthreads();
    if (tid == 0) {
        float t = 0.f;
        #pragma unroll
        for (int i = 0; i < 8; i++) t += red[i];
        g[row] = 1.f / (1.f + __expf(-(t + gb[0])));
    }
}

// ---------------- mix ----------------
__global__ void mix_kernel(const float* __restrict__ x, const float* __restrict__ ap,
                           const float* __restrict__ trn, const float* __restrict__ g,
                           float* __restrict__ o) {
    int idx = blockIdx.x * blockDim.x + threadIdx.x;
    if (idx >= Mrows * Cc / 4) return;
    float gg = g[idx / (Cc / 4)];
    float og = 1.f - gg;
    float4 xv = ((const float4*)x)[idx];
    float4 av = ((const float4*)ap)[idx];
    float4 tv = ((const float4*)trn)[idx];
    float4 ov = make_float4(xv.x + gg*av.x + og*tv.x,
                            xv.y + gg*av.y + og*tv.y,
                            xv.z + gg*av.z + og*tv.z,
                            xv.w + gg*av.w + og*tv.w);
    ((float4*)o)[idx] = ov;
}

// ---------------- silu(f1)*f2 -> f1 ----------------
__global__ void silumul_kernel(float* __restrict__ f1, const float* __restrict__ f2, int n4) {
    int idx = blockIdx.x * blockDim.x + threadIdx.x;
    if (idx >= n4) return;
    float4 a = ((const float4*)f1)[idx];
    float4 b = ((const float4*)f2)[idx];
    float4 o;
    o.x = a.x / (1.f + __expf(-a.x)) * b.x;
    o.y = a.y / (1.f + __expf(-a.y)) * b.y;
    o.z = a.z / (1.f + __expf(-a.z)) * b.z;
    o.w = a.w / (1.f + __expf(-a.w)) * b.w;
    ((float4*)f1)[idx] = o;
}

// ---------------- launch ----------------
extern "C" void kernel_launch(void* const* d_in, const int* in_sizes, int n_in,
                              void* d_out, int out_size) {
    const float* x          = (const float*)d_in[0];
    const float* norm1_w    = (const float*)d_in[1];
    const float* qkv_w      = (const float*)d_in[2];
    const float* qkv_b      = (const float*)d_in[3];
    const float* proj_w     = (const float*)d_in[4];
    const float* proj_b     = (const float*)d_in[5];
    const float* gate_w     = (const float*)d_in[6];
    const float* gate_b     = (const float*)d_in[7];
    const float* trn_win    = (const float*)d_in[8];
    const float* trn_wout   = (const float*)d_in[9];
    const float* trn_gate_w = (const float*)d_in[10];
    const float* trn_gate_b = (const float*)d_in[11];
    const float* trn_a      = (const float*)d_in[12];
    const float* trn_theta  = (const float*)d_in[13];
    const float* trn_scale  = (const float*)d_in[14];
    const float* norm2_w    = (const float*)d_in[15];
    const float* ffn_gate_w = (const float*)d_in[16];
    const float* ffn_up_w   = (const float*)d_in[17];
    const float* ffn_down_w = (const float*)d_in[18];
    float* out = (float*)d_out;

    float *h, *qkv, *ao, *proj, *u, *y, *tg, *trn, *gate, *x1, *f1, *f2;
    cudaGetSymbolAddress((void**)&h,    g_h);
    cudaGetSymbolAddress((void**)&qkv,  g_qkv);
    cudaGetSymbolAddress((void**)&ao,   g_ao);
    cudaGetSymbolAddress((void**)&proj, g_proj);
    cudaGetSymbolAddress((void**)&u,    g_u);
    cudaGetSymbolAddress((void**)&y,    g_y);
    cudaGetSymbolAddress((void**)&tg,   g_tg);
    cudaGetSymbolAddress((void**)&trn,  g_trn);
    cudaGetSymbolAddress((void**)&gate, g_gate);
    cudaGetSymbolAddress((void**)&x1,   g_x1);
    cudaGetSymbolAddress((void**)&f1,   g_f1);
    cudaGetSymbolAddress((void**)&f2,   g_f2);

    cudaFuncSetAttribute(attn_tiled, cudaFuncAttributeMaxDynamicSharedMemorySize, ATTN_SMEM);

    // 1) h = rms(x, norm1_w)
    rms_kernel<<<Mrows, 256>>>(x, norm1_w, h);
    // 2) qkv = h @ qkv_w^T + qkv_b
    sgemm<1><<<dim3(3 * Cc / BN, Mrows / BM), 256>>>(h, qkv_w, qkv_b, nullptr, qkv, Mrows, 3 * Cc, Cc);
    // 3) attention (tiled)
    attn_tiled<<<dim3(Tt / QT, Hh, Bb), 256, ATTN_SMEM>>>(qkv, ao);
    // 4) proj
    sgemm<1><<<dim3(Cc / BN, Mrows / BM), 256>>>(ao, proj_w, proj_b, nullptr, proj, Mrows, Cc, Cc);
    // 5) TRN branch
    gemm_skinny<<<Mrows / 16, dim3(32, 8)>>>(h, trn_win, nullptr, u, Cc, 0);
    gemm_skinny<<<Mrows / 16, dim3(32, 8)>>>(h, trn_gate_w, trn_gate_b, tg, Cc, 1);
    scan_kernel<<<Bb, 1024>>>(u, trn_a, trn_theta, y);
    trn_out_kernel<<<dim3(Mrows / 16, Cc / 64), dim3(64, 4)>>>(tg, y, trn_wout, trn_scale, trn);
    // 6) gate + mix
    gate_kernel<<<Mrows, 256>>>(h, gate_w, gate_b, gate);
    mix_kernel<<<(Mrows * Cc / 4 + 255) / 256, 256>>>(x, proj, trn, gate, x1);
    // 7) FFN
    rms_kernel<<<Mrows, 256>>>(x1, norm2_w, h);
    sgemm<0><<<dim3(DFFf / BN, Mrows / BM), 256>>>(h, ffn_gate_w, nullptr, nullptr, f1, Mrows, DFFf, Cc);
    sgemm<0><<<dim3(DFFf / BN, Mrows / BM), 256>>>(h, ffn_up_w, nullptr, nullptr, f2, Mrows, DFFf, Cc);
    silumul_kernel<<<((int)((size_t)Mrows * DFFf / 4) + 255) / 256, 256>>>(f1, f2, Mrows * (DFFf / 4));
    // 8) out = f1 @ ffn_down_w^T + x1
    sgemm<2><<<dim3(Cc / BN, Mrows / BM), 256>>>(f1, ffn_down_w, nullptr, x1, out, Mrows, Cc, DFFf);
}

// round 3
// speedup vs baseline: 1.9430x; 1.6237x over previous
#include <cuda_runtime.h>
#include <math.h>

#define Bb   2
#define Tt   2048
#define Cc   1024
#define Hh   16
#define DHd  64
#define WINw 256
#define Kk   32
#define DFFf 4096
#define Mrows (Bb*Tt)   // 4096

// ---------------- scratch ----------------
__device__ float g_h   [Mrows*Cc];
__device__ float g_qkv [Mrows*3*Cc];
__device__ float g_ao  [Mrows*Cc];
__device__ float g_proj[Mrows*Cc];
__device__ float g_u   [Mrows*Kk];
__device__ float g_y   [Mrows*Kk];
__device__ float g_tg  [Mrows*Kk];
__device__ float g_trn [Mrows*Cc];
__device__ float g_gate[Mrows];
__device__ float g_x1  [Mrows*Cc];
__device__ float g_f1  [(size_t)Mrows*DFFf];
__device__ float g_f2  [(size_t)Mrows*DFFf];

// ---------------- RMSNorm ----------------
__global__ void rms_kernel(const float* __restrict__ x, const float* __restrict__ w,
                           float* __restrict__ o) {
    int row = blockIdx.x;
    int tid = threadIdx.x;
    const float4* xr = (const float4*)(x + (size_t)row * Cc);
    float4 v = xr[tid];
    float s = v.x*v.x + v.y*v.y + v.z*v.z + v.w*v.w;
    __shared__ float red[8];
    int lane = tid & 31, warp = tid >> 5;
    #pragma unroll
    for (int o2 = 16; o2; o2 >>= 1) s += __shfl_xor_sync(0xffffffffu, s, o2);
    if (lane == 0) red[warp] = s;
    __syncthreads();
    if (warp == 0) {
        float t = (lane < 8) ? red[lane] : 0.f;
        #pragma unroll
        for (int o2 = 4; o2; o2 >>= 1) t += __shfl_xor_sync(0xffffffffu, t, o2);
        if (lane == 0) red[0] = t;
    }
    __syncthreads();
    float inv = rsqrtf(red[0] * (1.0f / Cc) + 1e-6f);
    float4 wv = ((const float4*)w)[tid];
    float4 ov = make_float4(v.x*inv*wv.x, v.y*inv*wv.y, v.z*inv*wv.z, v.w*inv*wv.w);
    ((float4*)(o + (size_t)row * Cc))[tid] = ov;
}

// ---------------- TF32 tensor-core GEMM: C[M,N] = A[M,K] @ W[N,K]^T ----------------
#define TBM 128
#define TBN 128
#define TBK 32
#define TLDK 36   // padded smem row (floats); 144 B, 16B-aligned

__device__ __forceinline__ unsigned f2tf(float f) {
    unsigned r;
    asm("cvt.rna.tf32.f32 %0, %1;" : "=r"(r) : "f"(f));
    return r;
}
__device__ __forceinline__ void cp_async16(unsigned sa, const float* gp) {
    asm volatile("cp.async.cg.shared.global [%0], [%1], 16;" :: "r"(sa), "l"(gp));
}
__device__ __forceinline__ void cp_commit() {
    asm volatile("cp.async.commit_group;");
}
template<int N>
__device__ __forceinline__ void cp_wait() {
    asm volatile("cp.async.wait_group %0;" :: "n"(N));
}
__device__ __forceinline__ void mma_tf32(float* d, const unsigned* a, const unsigned* b) {
    asm volatile(
        "mma.sync.aligned.m16n8k8.row.col.f32.tf32.tf32.f32 "
        "{%0,%1,%2,%3}, {%4,%5,%6,%7}, {%8,%9}, {%0,%1,%2,%3};"
        : "+f"(d[0]), "+f"(d[1]), "+f"(d[2]), "+f"(d[3])
        : "r"(a[0]), "r"(a[1]), "r"(a[2]), "r"(a[3]), "r"(b[0]), "r"(b[1]));
}

template<int EPI>  // 0 = none, 1 = +bias, 2 = +res
__global__ void __launch_bounds__(256, 2)
tgemm(const float* __restrict__ A, const float* __restrict__ W,
      const float* __restrict__ bias, const float* __restrict__ res,
      float* __restrict__ C, int M, int N, int Kd) {
    __shared__ float As[2][TBM][TLDK];
    __shared__ float Ws[2][TBN][TLDK];
    int tid = threadIdx.x;
    int lane = tid & 31, wid = tid >> 5;
    int g = lane >> 2, t = lane & 3;
    int wm = wid & 3, wn = wid >> 2;             // 4x2 warps, warp tile 32(m) x 64(n)
    int bm = blockIdx.y, bn = blockIdx.x;
    const float* Ap = A + (size_t)(bm * TBM) * Kd;
    const float* Wp = W + (size_t)(bn * TBN) * Kd;
    int lr = tid >> 3;              // 0..31
    int lc = (tid & 7) * 4;         // 0,4,..,28

    unsigned sa_a[2][4], sa_w[2][4];
    #pragma unroll
    for (int bf = 0; bf < 2; bf++)
        #pragma unroll
        for (int i = 0; i < 4; i++) {
            sa_a[bf][i] = (unsigned)__cvta_generic_to_shared(&As[bf][lr + i*32][lc]);
            sa_w[bf][i] = (unsigned)__cvta_generic_to_shared(&Ws[bf][lr + i*32][lc]);
        }

    int niter = Kd / TBK;
    // prologue: issue buffers 0 (and 1)
    #pragma unroll
    for (int i = 0; i < 4; i++) {
        cp_async16(sa_a[0][i], Ap + (size_t)(lr + i*32) * Kd + lc);
        cp_async16(sa_w[0][i], Wp + (size_t)(lr + i*32) * Kd + lc);
    }
    cp_commit();
    if (niter > 1) {
        #pragma unroll
        for (int i = 0; i < 4; i++) {
            cp_async16(sa_a[1][i], Ap + (size_t)(lr + i*32) * Kd + TBK + lc);
            cp_async16(sa_w[1][i], Wp + (size_t)(lr + i*32) * Kd + TBK + lc);
        }
        cp_commit();
    }

    float acc[2][8][4];
    #pragma unroll
    for (int mi = 0; mi < 2; mi++)
        #pragma unroll
        for (int ni = 0; ni < 8; ni++)
            #pragma unroll
            for (int j = 0; j < 4; j++) acc[mi][ni][j] = 0.f;

    for (int it = 0; it < niter; it++) {
        if (it + 1 < niter) cp_wait<1>(); else cp_wait<0>();
        __syncthreads();
        int buf = it & 1;
        #pragma unroll
        for (int ks = 0; ks < 4; ks++) {
            int k0 = ks * 8;
            unsigned afr[2][4];
            #pragma unroll
            for (int mi = 0; mi < 2; mi++) {
                int m = wm*32 + mi*16 + g;
                afr[mi][0] = f2tf(As[buf][m    ][k0 + t]);
                afr[mi][1] = f2tf(As[buf][m + 8][k0 + t]);
                afr[mi][2] = f2tf(As[buf][m    ][k0 + t + 4]);
                afr[mi][3] = f2tf(As[buf][m + 8][k0 + t + 4]);
            }
            unsigned bfr[8][2];
            #pragma unroll
            for (int ni = 0; ni < 8; ni++) {
                int n = wn*64 + ni*8 + g;
                bfr[ni][0] = f2tf(Ws[buf][n][k0 + t]);
                bfr[ni][1] = f2tf(Ws[buf][n][k0 + t + 4]);
            }
            #pragma unroll
            for (int mi = 0; mi < 2; mi++)
                #pragma unroll
                for (int ni = 0; ni < 8; ni++)
                    mma_tf32(acc[mi][ni], afr[mi], bfr[ni]);
        }
        __syncthreads();
        if (it + 2 < niter) {
            int k0 = (it + 2) * TBK;
            #pragma unroll
            for (int i = 0; i < 4; i++) {
                cp_async16(sa_a[buf][i], Ap + (size_t)(lr + i*32) * Kd + k0 + lc);
                cp_async16(sa_w[buf][i], Wp + (size_t)(lr + i*32) * Kd + k0 + lc);
            }
            cp_commit();
        }
    }

    // epilogue
    #pragma unroll
    for (int mi = 0; mi < 2; mi++) {
        #pragma unroll
        for (int ni = 0; ni < 8; ni++) {
            int row = bm*TBM + wm*32 + mi*16 + g;
            int col = bn*TBN + wn*64 + ni*8 + 2*t;
            float v0 = acc[mi][ni][0], v1 = acc[mi][ni][1];
            float v2 = acc[mi][ni][2], v3 = acc[mi][ni][3];
            if (EPI == 1) {
                float b0 = bias[col], b1 = bias[col + 1];
                v0 += b0; v1 += b1; v2 += b0; v3 += b1;
            }
            if (EPI == 2) {
                const float* r0 = res + (size_t)row * N + col;
                const float* r1 = res + (size_t)(row + 8) * N + col;
                v0 += r0[0]; v1 += r0[1]; v2 += r1[0]; v3 += r1[1];
            }
            float2 p01 = make_float2(v0, v1);
            float2 p23 = make_float2(v2, v3);
            *(float2*)&C[(size_t)row * N + col]        = p01;
            *(float2*)&C[(size_t)(row + 8) * N + col]  = p23;
        }
    }
}

// ---------------- tiled windowed attention ----------------
#define QT 64
#define NJ 384
#define PSL 388
#define ATTN_SMEM ((64*68*2 + 64*PSL + 64) * 4)

__global__ void attn_tiled(const float* __restrict__ qkv, float* __restrict__ ao) {
    extern __shared__ float sm[];
    float* Qs   = sm;
    float* KVs  = Qs + 64*68;
    float* Ps   = KVs + 64*68;
    float* rsum = Ps + 64*PSL;

    int q0 = blockIdx.x * QT;
    int h = blockIdx.y, b = blockIdx.z;
    int tid = threadIdx.x;
    const size_t rs = 3 * Cc;
    const float* qbase = qkv + (size_t)b * Tt * rs + h * DHd;

    for (int i = tid; i < 64*16; i += 256) {
        int r = i >> 4, c4 = (i & 15) * 4;
        *(float4*)&Qs[r*68 + c4] =
            *(const float4*)(qbase + (size_t)(q0 + r) * rs + c4);
    }
    int kbase = q0 - 256;
    int tx = tid & 15, ty = tid >> 4;

    for (int cc = 0; cc < 6; cc++) {
        for (int i = tid; i < 64*16; i += 256) {
            int r = i >> 4, c4 = (i & 15) * 4;
            int kg = kbase + cc*64 + r;
            float4 v = make_float4(0.f, 0.f, 0.f, 0.f);
            if (kg >= 0 && kg < Tt)
                v = *(const float4*)(qbase + Cc + (size_t)kg * rs + c4);
            *(float4*)&KVs[r*68 + c4] = v;
        }
        __syncthreads();

        float acc[4][4] = {};
        #pragma unroll 4
        for (int d = 0; d < 64; d += 4) {
            float4 qv[4], kv[4];
            #pragma unroll
            for (int r = 0; r < 4; r++) qv[r] = *(float4*)&Qs[(ty*4+r)*68 + d];
            #pragma unroll
            for (int c = 0; c < 4; c++) kv[c] = *(float4*)&KVs[(tx*4+c)*68 + d];
            #pragma unroll
            for (int r = 0; r < 4; r++)
                #pragma unroll
                for (int c = 0; c < 4; c++)
                    acc[r][c] += qv[r].x*kv[c].x + qv[r].y*kv[c].y
                               + qv[r].z*kv[c].z + qv[r].w*kv[c].w;
        }
        #pragma unroll
        for (int r = 0; r < 4; r++) {
            int qi = ty*4 + r;
            #pragma unroll
            for (int c = 0; c < 4; c++) {
                int j = cc*64 + tx*4 + c;
                int kg = kbase + j;
                bool valid = (j >= qi + 1) && (j <= qi + 256) && (kg >= 0);
                Ps[qi*PSL + j] = valid ? acc[r][c] * 0.125f : -1e30f;
            }
        }
        __syncthreads();
    }

    int lane = tid & 31, wrp = tid >> 5;
    for (int q = wrp; q < 64; q += 8) {
        float m = -INFINITY;
        for (int j = lane; j < NJ; j += 32) m = fmaxf(m, Ps[q*PSL + j]);
        #pragma unroll
        for (int o2 = 16; o2; o2 >>= 1) m = fmaxf(m, __shfl_xor_sync(0xffffffffu, m, o2));
        float s = 0.f;
        for (int j = lane; j < NJ; j += 32) {
            float e = __expf(Ps[q*PSL + j] - m);
            Ps[q*PSL + j] = e;
            s += e;
        }
        #pragma unroll
        for (int o2 = 16; o2; o2 >>= 1) s += __shfl_xor_sync(0xffffffffu, s, o2);
        if (lane == 0) rsum[q] = 1.0f / s;
    }
    __syncthreads();

    float4 o0 = make_float4(0,0,0,0), o1 = o0, o2v = o0, o3 = o0;
    for (int cc = 0; cc < 6; cc++) {
        for (int i = tid; i < 64*16; i += 256) {
            int r = i >> 4, c4 = (i & 15) * 4;
            int kg = kbase + cc*64 + r;
            float4 v = make_float4(0.f, 0.f, 0.f, 0.f);
            if (kg >= 0 && kg < Tt)
                v = *(const float4*)(qbase + 2*Cc + (size_t)kg * rs + c4);
            *(float4*)&KVs[r*68 + c4] = v;
        }
        __syncthreads();
        #pragma unroll 4
        for (int jj = 0; jj < 64; jj++) {
            int j = cc*64 + jj;
            float4 vv = *(float4*)&KVs[jj*68 + tx*4];
            float p0 = Ps[(ty*4+0)*PSL + j];
            float p1 = Ps[(ty*4+1)*PSL + j];
            float p2 = Ps[(ty*4+2)*PSL + j];
            float p3 = Ps[(ty*4+3)*PSL + j];
            o0.x += p0*vv.x; o0.y += p0*vv.y; o0.z += p0*vv.z; o0.w += p0*vv.w;
            o1.x += p1*vv.x; o1.y += p1*vv.y; o1.z += p1*vv.z; o1.w += p1*vv.w;
            o2v.x += p2*vv.x; o2v.y += p2*vv.y; o2v.z += p2*vv.z; o2v.w += p2*vv.w;
            o3.x += p3*vv.x; o3.y += p3*vv.y; o3.z += p3*vv.z; o3.w += p3*vv.w;
        }
        __syncthreads();
    }
    {
        float4 outs[4] = {o0, o1, o2v, o3};
        #pragma unroll
        for (int r = 0; r < 4; r++) {
            int q = ty*4 + r;
            float inv = rsum[q];
            float4 ov = outs[r];
            ov.x *= inv; ov.y *= inv; ov.z *= inv; ov.w *= inv;
            *(float4*)(ao + (size_t)(b*Tt + q0 + q)*Cc + h*DHd + tx*4) = ov;
        }
    }
}

// ---------------- skinny GEMM ----------------
__global__ void gemm_skinny(const float* __restrict__ A, const float* __restrict__ W,
                            const float* __restrict__ bias, float* __restrict__ Cmat,
                            int Kd, int do_sigmoid) {
    __shared__ float As[16][64];
    __shared__ float Ws[32][65];
    int tx = threadIdx.x, ty = threadIdx.y;
    int tid = ty * 32 + tx;
    int m0 = blockIdx.x * 16;
    float acc0 = 0.f, acc1 = 0.f;
    for (int k0 = 0; k0 < Kd; k0 += 64) {
        int r = tid >> 4, c4 = (tid & 15) * 4;
        float4 av = *(const float4*)&A[(size_t)(m0 + r) * Kd + k0 + c4];
        *(float4*)&As[r][c4] = av;
        int r2 = tid >> 3, c8 = (tid & 7) * 8;
        float4 w0 = *(const float4*)&W[(size_t)r2 * Kd + k0 + c8];
        float4 w1 = *(const float4*)&W[(size_t)r2 * Kd + k0 + c8 + 4];
        Ws[r2][c8+0]=w0.x; Ws[r2][c8+1]=w0.y; Ws[r2][c8+2]=w0.z; Ws[r2][c8+3]=w0.w;
        Ws[r2][c8+4]=w1.x; Ws[r2][c8+5]=w1.y; Ws[r2][c8+6]=w1.z; Ws[r2][c8+7]=w1.w;
        __syncthreads();
        #pragma unroll
        for (int kk = 0; kk < 64; kk++) {
            float wv = Ws[tx][kk];
            acc0 += As[ty][kk] * wv;
            acc1 += As[ty + 8][kk] * wv;
        }
        __syncthreads();
    }
    float b0 = bias ? bias[tx] : 0.f;
    float v0 = acc0 + b0, v1 = acc1 + b0;
    if (do_sigmoid) {
        v0 = 1.f / (1.f + __expf(-v0));
        v1 = 1.f / (1.f + __expf(-v1));
    }
    Cmat[(size_t)(m0 + ty) * Kk + tx]     = v0;
    Cmat[(size_t)(m0 + ty + 8) * Kk + tx] = v1;
}

// ---------------- chunked parallel oscillator scan ----------------
__global__ void scan_kernel(const float* __restrict__ u, const float* __restrict__ a_logit,
                            const float* __restrict__ theta, float* __restrict__ y) {
    __shared__ float ssr[32][33], ssi[32][33];
    int b = blockIdx.x;
    int tid = threadIdx.x;
    int k = tid & 31, c = tid >> 5;
    float a  = 1.f / (1.f + __expf(-a_logit[k]));
    float ct = cosf(theta[k]), st = sinf(theta[k]);
    const float* up = u + (size_t)b * Tt * Kk + k;
    int t0 = c * 64;

    float sr = 0.f, si = 0.f;
    for (int i = 0; i < 64; i++) {
        float ut = up[(size_t)(t0 + i) * Kk];
        float nsr = a * (ct * sr - st * si) + ut;
        float nsi = a * (st * sr + ct * si);
        sr = nsr; si = nsi;
    }
    ssr[c][k] = sr; ssi[c][k] = si;
    __syncthreads();

    if (tid < 32) {
        int kq = tid;
        float aq = 1.f / (1.f + __expf(-a_logit[kq]));
        float a64 = __powf(aq, 64.f);
        float th = theta[kq];
        float c64 = cosf(64.f * th), s64 = sinf(64.f * th);
        float M00 = a64 * c64, M01 = -a64 * s64;
        float M10 = a64 * s64, M11 =  a64 * c64;
        float cr = 0.f, ci = 0.f;
        for (int cc = 0; cc < 32; cc++) {
            float lr = ssr[cc][kq], li = ssi[cc][kq];
            ssr[cc][kq] = cr; ssi[cc][kq] = ci;
            float nr = M00 * cr + M01 * ci + lr;
            float ni = M10 * cr + M11 * ci + li;
            cr = nr; ci = ni;
        }
    }
    __syncthreads();

    sr = ssr[c][k]; si = ssi[c][k];
    float* yp = y + (size_t)b * Tt * Kk + k;
    for (int i = 0; i < 64; i++) {
        float ut = up[(size_t)(t0 + i) * Kk];
        float nsr = a * (ct * sr - st * si) + ut;
        float nsi = a * (st * sr + ct * si);
        sr = nsr; si = nsi;
        yp[(size_t)(t0 + i) * Kk] = sr;
    }
}

// ---------------- trn_out ----------------
__global__ void trn_out_kernel(const float* __restrict__ tg, const float* __restrict__ y,
                               const float* __restrict__ wout, const float* __restrict__ scale_p,
                               float* __restrict__ out) {
    __shared__ float Zs[16][33];
    __shared__ float Ws[64][33];
    int tx = threadIdx.x, ty = threadIdx.y;
    int tid = ty * 64 + tx;
    int m0 = blockIdx.x * 16, c0 = blockIdx.y * 64;
    for (int i = tid; i < 16 * Kk; i += 256) {
        int r = i >> 5, k = i & 31;
        size_t off = (size_t)(m0 + r) * Kk + k;
        Zs[r][k] = tg[off] * y[off];
    }
    for (int i = tid; i < 64 * Kk; i += 256) {
        int r = i >> 5, k = i & 31;
        Ws[r][k] = wout[(size_t)(c0 + r) * Kk + k];
    }
    __syncthreads();
    float scale = scale_p[0];
    float acc[4] = {0.f, 0.f, 0.f, 0.f};
    #pragma unroll
    for (int k = 0; k < Kk; k++) {
        float wv = Ws[tx][k];
        acc[0] += Zs[ty][k]      * wv;
        acc[1] += Zs[ty + 4][k]  * wv;
        acc[2] += Zs[ty + 8][k]  * wv;
        acc[3] += Zs[ty + 12][k] * wv;
    }
    #pragma unroll
    for (int r = 0; r < 4; r++)
        out[(size_t)(m0 + ty + 4 * r) * Cc + c0 + tx] = acc[r] * scale;
}

// ---------------- scalar gate ----------------
__global__ void gate_kernel(const float* __restrict__ h, const float* __restrict__ gw,
                            const float* __restrict__ gb, float* __restrict__ g) {
    int row = blockIdx.x, tid = threadIdx.x;
    float4 a = ((const float4*)(h + (size_t)row * Cc))[tid];
    float4 w = ((const float4*)gw)[tid];
    float s = a.x*w.x + a.y*w.y + a.z*w.z + a.w*w.w;
    __shared__ float red[8];
    int lane = tid & 31, warp = tid >> 5;
    #pragma unroll
    for (int o2 = 16; o2; o2 >>= 1) s += __shfl_xor_sync(0xffffffffu, s, o2);
    if (lane == 0) red[warp] = s;
    __syncthreads();
    if (tid == 0) {
        float t = 0.f;
        #pragma unroll
        for (int i = 0; i < 8; i++) t += red[i];
        g[row] = 1.f / (1.f + __expf(-(t + gb[0])));
    }
}

// ---------------- mix ----------------
__global__ void mix_kernel(const float* __restrict__ x, const float* __restrict__ ap,
                           const float* __restrict__ trn, const float* __restrict__ g,
                           float* __restrict__ o) {
    int idx = blockIdx.x * blockDim.x + threadIdx.x;
    if (idx >= Mrows * Cc / 4) return;
    float gg = g[idx / (Cc / 4)];
    float og = 1.f - gg;
    float4 xv = ((const float4*)x)[idx];
    float4 av = ((const float4*)ap)[idx];
    float4 tv = ((const float4*)trn)[idx];
    float4 ov = make_float4(xv.x + gg*av.x + og*tv.x,
                            xv.y + gg*av.y + og*tv.y,
                            xv.z + gg*av.z + og*tv.z,
                            xv.w + gg*av.w + og*tv.w);
    ((float4*)o)[idx] = ov;
}

// ---------------- silu(f1)*f2 -> f1 ----------------
__global__ void silumul_kernel(float* __restrict__ f1, const float* __restrict__ f2, int n4) {
    int idx = blockIdx.x * blockDim.x + threadIdx.x;
    if (idx >= n4) return;
    float4 a = ((const float4*)f1)[idx];
    float4 b = ((const float4*)f2)[idx];
    float4 o;
    o.x = a.x / (1.f + __expf(-a.x)) * b.x;
    o.y = a.y / (1.f + __expf(-a.y)) * b.y;
    o.z = a.z / (1.f + __expf(-a.z)) * b.z;
    o.w = a.w / (1.f + __expf(-a.w)) * b.w;
    ((float4*)f1)[idx] = o;
}

// ---------------- launch ----------------
extern "C" void kernel_launch(void* const* d_in, const int* in_sizes, int n_in,
                              void* d_out, int out_size) {
    const float* x          = (const float*)d_in[0];
    const float* norm1_w    = (const float*)d_in[1];
    const float* qkv_w      = (const float*)d_in[2];
    const float* qkv_b      = (const float*)d_in[3];
    const float* proj_w     = (const float*)d_in[4];
    const float* proj_b     = (const float*)d_in[5];
    const float* gate_w     = (const float*)d_in[6];
    const float* gate_b     = (const float*)d_in[7];
    const float* trn_win    = (const float*)d_in[8];
    const float* trn_wout   = (const float*)d_in[9];
    const float* trn_gate_w = (const float*)d_in[10];
    const float* trn_gate_b = (const float*)d_in[11];
    const float* trn_a      = (const float*)d_in[12];
    const float* trn_theta  = (const float*)d_in[13];
    const float* trn_scale  = (const float*)d_in[14];
    const float* norm2_w    = (const float*)d_in[15];
    const float* ffn_gate_w = (const float*)d_in[16];
    const float* ffn_up_w   = (const float*)d_in[17];
    const float* ffn_down_w = (const float*)d_in[18];
    float* out = (float*)d_out;

    float *h, *qkv, *ao, *proj, *u, *y, *tg, *trn, *gate, *x1, *f1, *f2;
    cudaGetSymbolAddress((void**)&h,    g_h);
    cudaGetSymbolAddress((void**)&qkv,  g_qkv);
    cudaGetSymbolAddress((void**)&ao,   g_ao);
    cudaGetSymbolAddress((void**)&proj, g_proj);
    cudaGetSymbolAddress((void**)&u,    g_u);
    cudaGetSymbolAddress((void**)&y,    g_y);
    cudaGetSymbolAddress((void**)&tg,   g_tg);
    cudaGetSymbolAddress((void**)&trn,  g_trn);
    cudaGetSymbolAddress((void**)&gate, g_gate);
    cudaGetSymbolAddress((void**)&x1,   g_x1);
    cudaGetSymbolAddress((void**)&f1,   g_f1);
    cudaGetSymbolAddress((void**)&f2,   g_f2);

    cudaFuncSetAttribute(attn_tiled, cudaFuncAttributeMaxDynamicSharedMemorySize, ATTN_SMEM);

    // 1) h = rms(x, norm1_w)
    rms_kernel<<<Mrows, 256>>>(x, norm1_w, h);
    // 2) qkv = h @ qkv_w^T + qkv_b
    tgemm<1><<<dim3(3 * Cc / TBN, Mrows / TBM), 256>>>(h, qkv_w, qkv_b, nullptr, qkv, Mrows, 3 * Cc, Cc);
    // 3) attention
    attn_tiled<<<dim3(Tt / QT, Hh, Bb), 256, ATTN_SMEM>>>(qkv, ao);
    // 4) proj
    tgemm<1><<<dim3(Cc / TBN, Mrows / TBM), 256>>>(ao, proj_w, proj_b, nullptr, proj, Mrows, Cc, Cc);
    // 5) TRN branch
    gemm_skinny<<<Mrows / 16, dim3(32, 8)>>>(h, trn_win, nullptr, u, Cc, 0);
    gemm_skinny<<<Mrows / 16, dim3(32, 8)>>>(h, trn_gate_w, trn_gate_b, tg, Cc, 1);
    scan_kernel<<<Bb, 1024>>>(u, trn_a, trn_theta, y);
    trn_out_kernel<<<dim3(Mrows / 16, Cc / 64), dim3(64, 4)>>>(tg, y, trn_wout, trn_scale, trn);
    // 6) gate + mix
    gate_kernel<<<Mrows, 256>>>(h, gate_w, gate_b, gate);
    mix_kernel<<<(Mrows * Cc / 4 + 255) / 256, 256>>>(x, proj, trn, gate, x1);
    // 7) FFN
    rms_kernel<<<Mrows, 256>>>(x1, norm2_w, h);
    tgemm<0><<<dim3(DFFf / TBN, Mrows / TBM), 256>>>(h, ffn_gate_w, nullptr, nullptr, f1, Mrows, DFFf, Cc);
    tgemm<0><<<dim3(DFFf / TBN, Mrows / TBM), 256>>>(h, ffn_up_w, nullptr, nullptr, f2, Mrows, DFFf, Cc);
    silumul_kernel<<<((int)((size_t)Mrows * DFFf / 4) + 255) / 256, 256>>>(f1, f2, Mrows * (DFFf / 4));
    // 8) out = f1 @ ffn_down_w^T + x1
    tgemm<2><<<dim3(Cc / TBN, Mrows / TBM), 256>>>(f1, ffn_down_w, nullptr, x1, out, Mrows, Cc, DFFf);
}

// round 4
// speedup vs baseline: 3.0447x; 1.5670x over previous
#include <cuda_runtime.h>
#include <math.h>

#define Bb   2
#define Tt   2048
#define Cc   1024
#define Hh   16
#define DHd  64
#define WINw 256
#define Kk   32
#define DFFf 4096
#define Mrows (Bb*Tt)   // 4096

// ---------------- scratch ----------------
__device__ float g_h   [Mrows*Cc];
__device__ float g_qkv [Mrows*3*Cc];
__device__ float g_ao  [Mrows*Cc];
__device__ float g_proj[Mrows*Cc];
__device__ float g_u   [Mrows*Kk];
__device__ float g_y   [Mrows*Kk];
__device__ float g_tg  [Mrows*Kk];
__device__ float g_trn [Mrows*Cc];
__device__ float g_gate[Mrows];
__device__ float g_x1  [Mrows*Cc];
__device__ float g_f1  [(size_t)Mrows*DFFf];
__device__ float g_f2  [(size_t)Mrows*DFFf];
// tf32-rounded weight copies
__device__ float g_wq [3*Cc*Cc];
__device__ float g_wp [Cc*Cc];
__device__ float g_wg [(size_t)DFFf*Cc];
__device__ float g_wu [(size_t)DFFf*Cc];
__device__ float g_wd [(size_t)Cc*DFFf];

__device__ __forceinline__ unsigned f2tf(float f) {
    unsigned r;
    asm("cvt.rna.tf32.f32 %0, %1;" : "=r"(r) : "f"(f));
    return r;
}
__device__ __forceinline__ float tf32r(float f) {
    return __uint_as_float(f2tf(f));
}

// ---------------- weight tf32 pre-round ----------------
__global__ void round_tf32_kernel(const float* __restrict__ in, float* __restrict__ out, int n4) {
    int idx = blockIdx.x * blockDim.x + threadIdx.x;
    if (idx >= n4) return;
    float4 v = ((const float4*)in)[idx];
    v.x = tf32r(v.x); v.y = tf32r(v.y); v.z = tf32r(v.z); v.w = tf32r(v.w);
    ((float4*)out)[idx] = v;
}

// ---------------- RMSNorm (tf32-rounded output) ----------------
__global__ void rms_kernel(const float* __restrict__ x, const float* __restrict__ w,
                           float* __restrict__ o) {
    int row = blockIdx.x;
    int tid = threadIdx.x;
    const float4* xr = (const float4*)(x + (size_t)row * Cc);
    float4 v = xr[tid];
    float s = v.x*v.x + v.y*v.y + v.z*v.z + v.w*v.w;
    __shared__ float red[8];
    int lane = tid & 31, warp = tid >> 5;
    #pragma unroll
    for (int o2 = 16; o2; o2 >>= 1) s += __shfl_xor_sync(0xffffffffu, s, o2);
    if (lane == 0) red[warp] = s;
    __syncthreads();
    if (warp == 0) {
        float t = (lane < 8) ? red[lane] : 0.f;
        #pragma unroll
        for (int o2 = 4; o2; o2 >>= 1) t += __shfl_xor_sync(0xffffffffu, t, o2);
        if (lane == 0) red[0] = t;
    }
    __syncthreads();
    float inv = rsqrtf(red[0] * (1.0f / Cc) + 1e-6f);
    float4 wv = ((const float4*)w)[tid];
    float4 ov = make_float4(tf32r(v.x*inv*wv.x), tf32r(v.y*inv*wv.y),
                            tf32r(v.z*inv*wv.z), tf32r(v.w*inv*wv.w));
    ((float4*)(o + (size_t)row * Cc))[tid] = ov;
}

// ---------------- TF32 tensor-core GEMM (operands pre-rounded; no CVT inside) ----------------
#define TBM 128
#define TBN 128
#define TBK 32
#define TLDK 36

__device__ __forceinline__ void cp_async16(unsigned sa, const float* gp) {
    asm volatile("cp.async.cg.shared.global [%0], [%1], 16;" :: "r"(sa), "l"(gp));
}
__device__ __forceinline__ void cp_commit() {
    asm volatile("cp.async.commit_group;");
}
template<int N>
__device__ __forceinline__ void cp_wait() {
    asm volatile("cp.async.wait_group %0;" :: "n"(N));
}
__device__ __forceinline__ void mma_tf32(float* d, const unsigned* a, const unsigned* b) {
    asm volatile(
        "mma.sync.aligned.m16n8k8.row.col.f32.tf32.tf32.f32 "
        "{%0,%1,%2,%3}, {%4,%5,%6,%7}, {%8,%9}, {%0,%1,%2,%3};"
        : "+f"(d[0]), "+f"(d[1]), "+f"(d[2]), "+f"(d[3])
        : "r"(a[0]), "r"(a[1]), "r"(a[2]), "r"(a[3]), "r"(b[0]), "r"(b[1]));
}

template<int EPI>  // 0 = none, 1 = +bias, 2 = +res
__global__ void __launch_bounds__(256, 2)
tgemm(const float* __restrict__ A, const float* __restrict__ W,
      const float* __restrict__ bias, const float* __restrict__ res,
      float* __restrict__ C, int M, int N, int Kd) {
    __shared__ float As[2][TBM][TLDK];
    __shared__ float Ws[2][TBN][TLDK];
    int tid = threadIdx.x;
    int lane = tid & 31, wid = tid >> 5;
    int g = lane >> 2, t = lane & 3;
    int wm = wid & 3, wn = wid >> 2;
    int bm = blockIdx.y, bn = blockIdx.x;
    const float* Ap = A + (size_t)(bm * TBM) * Kd;
    const float* Wp = W + (size_t)(bn * TBN) * Kd;
    int lr = tid >> 3;
    int lc = (tid & 7) * 4;

    unsigned sa_a[2][4], sa_w[2][4];
    #pragma unroll
    for (int bf = 0; bf < 2; bf++)
        #pragma unroll
        for (int i = 0; i < 4; i++) {
            sa_a[bf][i] = (unsigned)__cvta_generic_to_shared(&As[bf][lr + i*32][lc]);
            sa_w[bf][i] = (unsigned)__cvta_generic_to_shared(&Ws[bf][lr + i*32][lc]);
        }

    int niter = Kd / TBK;
    #pragma unroll
    for (int i = 0; i < 4; i++) {
        cp_async16(sa_a[0][i], Ap + (size_t)(lr + i*32) * Kd + lc);
        cp_async16(sa_w[0][i], Wp + (size_t)(lr + i*32) * Kd + lc);
    }
    cp_commit();
    if (niter > 1) {
        #pragma unroll
        for (int i = 0; i < 4; i++) {
            cp_async16(sa_a[1][i], Ap + (size_t)(lr + i*32) * Kd + TBK + lc);
            cp_async16(sa_w[1][i], Wp + (size_t)(lr + i*32) * Kd + TBK + lc);
        }
        cp_commit();
    }

    float acc[2][8][4];
    #pragma unroll
    for (int mi = 0; mi < 2; mi++)
        #pragma unroll
        for (int ni = 0; ni < 8; ni++)
            #pragma unroll
            for (int j = 0; j < 4; j++) acc[mi][ni][j] = 0.f;

    for (int it = 0; it < niter; it++) {
        if (it + 1 < niter) cp_wait<1>(); else cp_wait<0>();
        __syncthreads();
        int buf = it & 1;
        #pragma unroll
        for (int ks = 0; ks < 4; ks++) {
            int k0 = ks * 8;
            unsigned afr[2][4];
            #pragma unroll
            for (int mi = 0; mi < 2; mi++) {
                int m = wm*32 + mi*16 + g;
                afr[mi][0] = __float_as_uint(As[buf][m    ][k0 + t]);
                afr[mi][1] = __float_as_uint(As[buf][m + 8][k0 + t]);
                afr[mi][2] = __float_as_uint(As[buf][m    ][k0 + t + 4]);
                afr[mi][3] = __float_as_uint(As[buf][m + 8][k0 + t + 4]);
            }
            unsigned bfr[8][2];
            #pragma unroll
            for (int ni = 0; ni < 8; ni++) {
                int n = wn*64 + ni*8 + g;
                bfr[ni][0] = __float_as_uint(Ws[buf][n][k0 + t]);
                bfr[ni][1] = __float_as_uint(Ws[buf][n][k0 + t + 4]);
            }
            #pragma unroll
            for (int mi = 0; mi < 2; mi++)
                #pragma unroll
                for (int ni = 0; ni < 8; ni++)
                    mma_tf32(acc[mi][ni], afr[mi], bfr[ni]);
        }
        __syncthreads();
        if (it + 2 < niter) {
            int k0 = (it + 2) * TBK;
            #pragma unroll
            for (int i = 0; i < 4; i++) {
                cp_async16(sa_a[buf][i], Ap + (size_t)(lr + i*32) * Kd + k0 + lc);
                cp_async16(sa_w[buf][i], Wp + (size_t)(lr + i*32) * Kd + k0 + lc);
            }
            cp_commit();
        }
    }

    #pragma unroll
    for (int mi = 0; mi < 2; mi++) {
        #pragma unroll
        for (int ni = 0; ni < 8; ni++) {
            int row = bm*TBM + wm*32 + mi*16 + g;
            int col = bn*TBN + wn*64 + ni*8 + 2*t;
            float v0 = acc[mi][ni][0], v1 = acc[mi][ni][1];
            float v2 = acc[mi][ni][2], v3 = acc[mi][ni][3];
            if (EPI == 1) {
                float b0 = bias[col], b1 = bias[col + 1];
                v0 += b0; v1 += b1; v2 += b0; v3 += b1;
            }
            if (EPI == 2) {
                const float* r0 = res + (size_t)row * N + col;
                const float* r1 = res + (size_t)(row + 8) * N + col;
                v0 += r0[0]; v1 += r0[1]; v2 += r1[0]; v3 += r1[1];
            }
            *(float2*)&C[(size_t)row * N + col]       = make_float2(v0, v1);
            *(float2*)&C[(size_t)(row + 8) * N + col] = make_float2(v2, v3);
        }
    }
}

// ---------------- tiled windowed attention (output tf32-rounded) ----------------
#define QT 64
#define NJ 384
#define PSL 388
#define ATTN_SMEM ((64*68*2 + 64*PSL + 64) * 4)

__global__ void attn_tiled(const float* __restrict__ qkv, float* __restrict__ ao) {
    extern __shared__ float sm[];
    float* Qs   = sm;
    float* KVs  = Qs + 64*68;
    float* Ps   = KVs + 64*68;
    float* rsum = Ps + 64*PSL;

    int q0 = blockIdx.x * QT;
    int h = blockIdx.y, b = blockIdx.z;
    int tid = threadIdx.x;
    const size_t rs = 3 * Cc;
    const float* qbase = qkv + (size_t)b * Tt * rs + h * DHd;

    for (int i = tid; i < 64*16; i += 256) {
        int r = i >> 4, c4 = (i & 15) * 4;
        *(float4*)&Qs[r*68 + c4] =
            *(const float4*)(qbase + (size_t)(q0 + r) * rs + c4);
    }
    int kbase = q0 - 256;
    int tx = tid & 15, ty = tid >> 4;

    for (int cc = 0; cc < 6; cc++) {
        for (int i = tid; i < 64*16; i += 256) {
            int r = i >> 4, c4 = (i & 15) * 4;
            int kg = kbase + cc*64 + r;
            float4 v = make_float4(0.f, 0.f, 0.f, 0.f);
            if (kg >= 0 && kg < Tt)
                v = *(const float4*)(qbase + Cc + (size_t)kg * rs + c4);
            *(float4*)&KVs[r*68 + c4] = v;
        }
        __syncthreads();

        float acc[4][4] = {};
        #pragma unroll 4
        for (int d = 0; d < 64; d += 4) {
            float4 qv[4], kv[4];
            #pragma unroll
            for (int r = 0; r < 4; r++) qv[r] = *(float4*)&Qs[(ty*4+r)*68 + d];
            #pragma unroll
            for (int c = 0; c < 4; c++) kv[c] = *(float4*)&KVs[(tx*4+c)*68 + d];
            #pragma unroll
            for (int r = 0; r < 4; r++)
                #pragma unroll
                for (int c = 0; c < 4; c++)
                    acc[r][c] += qv[r].x*kv[c].x + qv[r].y*kv[c].y
                               + qv[r].z*kv[c].z + qv[r].w*kv[c].w;
        }
        #pragma unroll
        for (int r = 0; r < 4; r++) {
            int qi = ty*4 + r;
            #pragma unroll
            for (int c = 0; c < 4; c++) {
                int j = cc*64 + tx*4 + c;
                int kg = kbase + j;
                bool valid = (j >= qi + 1) && (j <= qi + 256) && (kg >= 0);
                Ps[qi*PSL + j] = valid ? acc[r][c] * 0.125f : -1e30f;
            }
        }
        __syncthreads();
    }

    int lane = tid & 31, wrp = tid >> 5;
    for (int q = wrp; q < 64; q += 8) {
        float m = -INFINITY;
        for (int j = lane; j < NJ; j += 32) m = fmaxf(m, Ps[q*PSL + j]);
        #pragma unroll
        for (int o2 = 16; o2; o2 >>= 1) m = fmaxf(m, __shfl_xor_sync(0xffffffffu, m, o2));
        float s = 0.f;
        for (int j = lane; j < NJ; j += 32) {
            float e = __expf(Ps[q*PSL + j] - m);
            Ps[q*PSL + j] = e;
            s += e;
        }
        #pragma unroll
        for (int o2 = 16; o2; o2 >>= 1) s += __shfl_xor_sync(0xffffffffu, s, o2);
        if (lane == 0) rsum[q] = 1.0f / s;
    }
    __syncthreads();

    float4 o0 = make_float4(0,0,0,0), o1 = o0, o2v = o0, o3 = o0;
    for (int cc = 0; cc < 6; cc++) {
        for (int i = tid; i < 64*16; i += 256) {
            int r = i >> 4, c4 = (i & 15) * 4;
            int kg = kbase + cc*64 + r;
            float4 v = make_float4(0.f, 0.f, 0.f, 0.f);
            if (kg >= 0 && kg < Tt)
                v = *(const float4*)(qbase + 2*Cc + (size_t)kg * rs + c4);
            *(float4*)&KVs[r*68 + c4] = v;
        }
        __syncthreads();
        #pragma unroll 4
        for (int jj = 0; jj < 64; jj++) {
            int j = cc*64 + jj;
            float4 vv = *(float4*)&KVs[jj*68 + tx*4];
            float p0 = Ps[(ty*4+0)*PSL + j];
            float p1 = Ps[(ty*4+1)*PSL + j];
            float p2 = Ps[(ty*4+2)*PSL + j];
            float p3 = Ps[(ty*4+3)*PSL + j];
            o0.x += p0*vv.x; o0.y += p0*vv.y; o0.z += p0*vv.z; o0.w += p0*vv.w;
            o1.x += p1*vv.x; o1.y += p1*vv.y; o1.z += p1*vv.z; o1.w += p1*vv.w;
            o2v.x += p2*vv.x; o2v.y += p2*vv.y; o2v.z += p2*vv.z; o2v.w += p2*vv.w;
            o3.x += p3*vv.x; o3.y += p3*vv.y; o3.z += p3*vv.z; o3.w += p3*vv.w;
        }
        __syncthreads();
    }
    {
        float4 outs[4] = {o0, o1, o2v, o3};
        #pragma unroll
        for (int r = 0; r < 4; r++) {
            int q = ty*4 + r;
            float inv = rsum[q];
            float4 ov = outs[r];
            ov.x = tf32r(ov.x * inv); ov.y = tf32r(ov.y * inv);
            ov.z = tf32r(ov.z * inv); ov.w = tf32r(ov.w * inv);
            *(float4*)(ao + (size_t)(b*Tt + q0 + q)*Cc + h*DHd + tx*4) = ov;
        }
    }
}

// ---------------- skinny GEMM ----------------
__global__ void gemm_skinny(const float* __restrict__ A, const float* __restrict__ W,
                            const float* __restrict__ bias, float* __restrict__ Cmat,
                            int Kd, int do_sigmoid) {
    __shared__ float As[16][64];
    __shared__ float Ws[32][65];
    int tx = threadIdx.x, ty = threadIdx.y;
    int tid = ty * 32 + tx;
    int m0 = blockIdx.x * 16;
    float acc0 = 0.f, acc1 = 0.f;
    for (int k0 = 0; k0 < Kd; k0 += 64) {
        int r = tid >> 4, c4 = (tid & 15) * 4;
        float4 av = *(const float4*)&A[(size_t)(m0 + r) * Kd + k0 + c4];
        *(float4*)&As[r][c4] = av;
        int r2 = tid >> 3, c8 = (tid & 7) * 8;
        float4 w0 = *(const float4*)&W[(size_t)r2 * Kd + k0 + c8];
        float4 w1 = *(const float4*)&W[(size_t)r2 * Kd + k0 + c8 + 4];
        Ws[r2][c8+0]=w0.x; Ws[r2][c8+1]=w0.y; Ws[r2][c8+2]=w0.z; Ws[r2][c8+3]=w0.w;
        Ws[r2][c8+4]=w1.x; Ws[r2][c8+5]=w1.y; Ws[r2][c8+6]=w1.z; Ws[r2][c8+7]=w1.w;
        __syncthreads();
        #pragma unroll
        for (int kk = 0; kk < 64; kk++) {
            float wv = Ws[tx][kk];
            acc0 += As[ty][kk] * wv;
            acc1 += As[ty + 8][kk] * wv;
        }
        __syncthreads();
    }
    float b0 = bias ? bias[tx] : 0.f;
    float v0 = acc0 + b0, v1 = acc1 + b0;
    if (do_sigmoid) {
        v0 = 1.f / (1.f + __expf(-v0));
        v1 = 1.f / (1.f + __expf(-v1));
    }
    Cmat[(size_t)(m0 + ty) * Kk + tx]     = v0;
    Cmat[(size_t)(m0 + ty + 8) * Kk + tx] = v1;
}

// ---------------- chunked parallel oscillator scan ----------------
__global__ void scan_kernel(const float* __restrict__ u, const float* __restrict__ a_logit,
                            const float* __restrict__ theta, float* __restrict__ y) {
    __shared__ float ssr[32][33], ssi[32][33];
    int b = blockIdx.x;
    int tid = threadIdx.x;
    int k = tid & 31, c = tid >> 5;
    float a  = 1.f / (1.f + __expf(-a_logit[k]));
    float ct = cosf(theta[k]), st = sinf(theta[k]);
    const float* up = u + (size_t)b * Tt * Kk + k;
    int t0 = c * 64;

    float sr = 0.f, si = 0.f;
    for (int i = 0; i < 64; i++) {
        float ut = up[(size_t)(t0 + i) * Kk];
        float nsr = a * (ct * sr - st * si) + ut;
        float nsi = a * (st * sr + ct * si);
        sr = nsr; si = nsi;
    }
    ssr[c][k] = sr; ssi[c][k] = si;
    __syncthreads();

    if (tid < 32) {
        int kq = tid;
        float aq = 1.f / (1.f + __expf(-a_logit[kq]));
        float a64 = __powf(aq, 64.f);
        float th = theta[kq];
        float c64 = cosf(64.f * th), s64 = sinf(64.f * th);
        float M00 = a64 * c64, M01 = -a64 * s64;
        float M10 = a64 * s64, M11 =  a64 * c64;
        float cr = 0.f, ci = 0.f;
        for (int cc = 0; cc < 32; cc++) {
            float lr = ssr[cc][kq], li = ssi[cc][kq];
            ssr[cc][kq] = cr; ssi[cc][kq] = ci;
            float nr = M00 * cr + M01 * ci + lr;
            float ni = M10 * cr + M11 * ci + li;
            cr = nr; ci = ni;
        }
    }
    __syncthreads();

    sr = ssr[c][k]; si = ssi[c][k];
    float* yp = y + (size_t)b * Tt * Kk + k;
    for (int i = 0; i < 64; i++) {
        float ut = up[(size_t)(t0 + i) * Kk];
        float nsr = a * (ct * sr - st * si) + ut;
        float nsi = a * (st * sr + ct * si);
        sr = nsr; si = nsi;
        yp[(size_t)(t0 + i) * Kk] = sr;
    }
}

// ---------------- trn_out ----------------
__global__ void trn_out_kernel(const float* __restrict__ tg, const float* __restrict__ y,
                               const float* __restrict__ wout, const float* __restrict__ scale_p,
                               float* __restrict__ out) {
    __shared__ float Zs[16][33];
    __shared__ float Ws[64][33];
    int tx = threadIdx.x, ty = threadIdx.y;
    int tid = ty * 64 + tx;
    int m0 = blockIdx.x * 16, c0 = blockIdx.y * 64;
    for (int i = tid; i < 16 * Kk; i += 256) {
        int r = i >> 5, k = i & 31;
        size_t off = (size_t)(m0 + r) * Kk + k;
        Zs[r][k] = tg[off] * y[off];
    }
    for (int i = tid; i < 64 * Kk; i += 256) {
        int r = i >> 5, k = i & 31;
        Ws[r][k] = wout[(size_t)(c0 + r) * Kk + k];
    }
    __syncthreads();
    float scale = scale_p[0];
    float acc[4] = {0.f, 0.f, 0.f, 0.f};
    #pragma unroll
    for (int k = 0; k < Kk; k++) {
        float wv = Ws[tx][k];
        acc[0] += Zs[ty][k]      * wv;
        acc[1] += Zs[ty + 4][k]  * wv;
        acc[2] += Zs[ty + 8][k]  * wv;
        acc[3] += Zs[ty + 12][k] * wv;
    }
    #pragma unroll
    for (int r = 0; r < 4; r++)
        out[(size_t)(m0 + ty + 4 * r) * Cc + c0 + tx] = acc[r] * scale;
}

// ---------------- scalar gate ----------------
__global__ void gate_kernel(const float* __restrict__ h, const float* __restrict__ gw,
                            const float* __restrict__ gb, float* __restrict__ g) {
    int row = blockIdx.x, tid = threadIdx.x;
    float4 a = ((const float4*)(h + (size_t)row * Cc))[tid];
    float4 w = ((const float4*)gw)[tid];
    float s = a.x*w.x + a.y*w.y + a.z*w.z + a.w*w.w;
    __shared__ float red[8];
    int lane = tid & 31, warp = tid >> 5;
    #pragma unroll
    for (int o2 = 16; o2; o2 >>= 1) s += __shfl_xor_sync(0xffffffffu, s, o2);
    if (lane == 0) red[warp] = s;
    __syncthreads();
    if (tid == 0) {
        float t = 0.f;
        #pragma unroll
        for (int i = 0; i < 8; i++) t += red[i];
        g[row] = 1.f / (1.f + __expf(-(t + gb[0])));
    }
}

// ---------------- mix ----------------
__global__ void mix_kernel(const float* __restrict__ x, const float* __restrict__ ap,
                           const float* __restrict__ trn, const float* __restrict__ g,
                           float* __restrict__ o) {
    int idx = blockIdx.x * blockDim.x + threadIdx.x;
    if (idx >= Mrows * Cc / 4) return;
    float gg = g[idx / (Cc / 4)];
    float og = 1.f - gg;
    float4 xv = ((const float4*)x)[idx];
    float4 av = ((const float4*)ap)[idx];
    float4 tv = ((const float4*)trn)[idx];
    float4 ov = make_float4(xv.x + gg*av.x + og*tv.x,
                            xv.y + gg*av.y + og*tv.y,
                            xv.z + gg*av.z + og*tv.z,
                            xv.w + gg*av.w + og*tv.w);
    ((float4*)o)[idx] = ov;
}

// ---------------- silu(f1)*f2 -> f1 (tf32-rounded: GEMM A operand) ----------------
__global__ void silumul_kernel(float* __restrict__ f1, const float* __restrict__ f2, int n4) {
    int idx = blockIdx.x * blockDim.x + threadIdx.x;
    if (idx >= n4) return;
    float4 a = ((const float4*)f1)[idx];
    float4 b = ((const float4*)f2)[idx];
    float4 o;
    o.x = tf32r(a.x / (1.f + __expf(-a.x)) * b.x);
    o.y = tf32r(a.y / (1.f + __expf(-a.y)) * b.y);
    o.z = tf32r(a.z / (1.f + __expf(-a.z)) * b.z);
    o.w = tf32r(a.w / (1.f + __expf(-a.w)) * b.w);
    ((float4*)f1)[idx] = o;
}

// ---------------- launch ----------------
extern "C" void kernel_launch(void* const* d_in, const int* in_sizes, int n_in,
                              void* d_out, int out_size) {
    const float* x          = (const float*)d_in[0];
    const float* norm1_w    = (const float*)d_in[1];
    const float* qkv_w      = (const float*)d_in[2];
    const float* qkv_b      = (const float*)d_in[3];
    const float* proj_w     = (const float*)d_in[4];
    const float* proj_b     = (const float*)d_in[5];
    const float* gate_w     = (const float*)d_in[6];
    const float* gate_b     = (const float*)d_in[7];
    const float* trn_win    = (const float*)d_in[8];
    const float* trn_wout   = (const float*)d_in[9];
    const float* trn_gate_w = (const float*)d_in[10];
    const float* trn_gate_b = (const float*)d_in[11];
    const float* trn_a      = (const float*)d_in[12];
    const float* trn_theta  = (const float*)d_in[13];
    const float* trn_scale  = (const float*)d_in[14];
    const float* norm2_w    = (const float*)d_in[15];
    const float* ffn_gate_w = (const float*)d_in[16];
    const float* ffn_up_w   = (const float*)d_in[17];
    const float* ffn_down_w = (const float*)d_in[18];
    float* out = (float*)d_out;

    float *h, *qkv, *ao, *proj, *u, *y, *tg, *trn, *gate, *x1, *f1, *f2;
    float *wq, *wp, *wg, *wu, *wd;
    cudaGetSymbolAddress((void**)&h,    g_h);
    cudaGetSymbolAddress((void**)&qkv,  g_qkv);
    cudaGetSymbolAddress((void**)&ao,   g_ao);
    cudaGetSymbolAddress((void**)&proj, g_proj);
    cudaGetSymbolAddress((void**)&u,    g_u);
    cudaGetSymbolAddress((void**)&y,    g_y);
    cudaGetSymbolAddress((void**)&tg,   g_tg);
    cudaGetSymbolAddress((void**)&trn,  g_trn);
    cudaGetSymbolAddress((void**)&gate, g_gate);
    cudaGetSymbolAddress((void**)&x1,   g_x1);
    cudaGetSymbolAddress((void**)&f1,   g_f1);
    cudaGetSymbolAddress((void**)&f2,   g_f2);
    cudaGetSymbolAddress((void**)&wq,   g_wq);
    cudaGetSymbolAddress((void**)&wp,   g_wp);
    cudaGetSymbolAddress((void**)&wg,   g_wg);
    cudaGetSymbolAddress((void**)&wu,   g_wu);
    cudaGetSymbolAddress((void**)&wd,   g_wd);

    cudaFuncSetAttribute(attn_tiled, cudaFuncAttributeMaxDynamicSharedMemorySize, ATTN_SMEM);

    // 0) pre-round weights to tf32 (bit-exact with in-GEMM cvt, but done once)
    {
        int n4q = 3*Cc*Cc/4, n4p = Cc*Cc/4, n4f = DFFf*Cc/4;
        round_tf32_kernel<<<(n4q+255)/256, 256>>>(qkv_w, wq, n4q);
        round_tf32_kernel<<<(n4p+255)/256, 256>>>(proj_w, wp, n4p);
        round_tf32_kernel<<<(n4f+255)/256, 256>>>(ffn_gate_w, wg, n4f);
        round_tf32_kernel<<<(n4f+255)/256, 256>>>(ffn_up_w,   wu, n4f);
        round_tf32_kernel<<<(n4f+255)/256, 256>>>(ffn_down_w, wd, n4f);
    }

    // 1) h = rms(x, norm1_w)  [tf32-rounded]
    rms_kernel<<<Mrows, 256>>>(x, norm1_w, h);
    // 2) qkv = h @ qkv_w^T + qkv_b
    tgemm<1><<<dim3(3 * Cc / TBN, Mrows / TBM), 256>>>(h, wq, qkv_b, nullptr, qkv, Mrows, 3 * Cc, Cc);
    // 3) attention
    attn_tiled<<<dim3(Tt / QT, Hh, Bb), 256, ATTN_SMEM>>>(qkv, ao);
    // 4) proj
    tgemm<1><<<dim3(Cc / TBN, Mrows / TBM), 256>>>(ao, wp, proj_b, nullptr, proj, Mrows, Cc, Cc);
    // 5) TRN branch
    gemm_skinny<<<Mrows / 16, dim3(32, 8)>>>(h, trn_win, nullptr, u, Cc, 0);
    gemm_skinny<<<Mrows / 16, dim3(32, 8)>>>(h, trn_gate_w, trn_gate_b, tg, Cc, 1);
    scan_kernel<<<Bb, 1024>>>(u, trn_a, trn_theta, y);
    trn_out_kernel<<<dim3(Mrows / 16, Cc / 64), dim3(64, 4)>>>(tg, y, trn_wout, trn_scale, trn);
    // 6) gate + mix
    gate_kernel<<<Mrows, 256>>>(h, gate_w, gate_b, gate);
    mix_kernel<<<(Mrows * Cc / 4 + 255) / 256, 256>>>(x, proj, trn, gate, x1);
    // 7) FFN
    rms_kernel<<<Mrows, 256>>>(x1, norm2_w, h);
    tgemm<0><<<dim3(DFFf / TBN, Mrows / TBM), 256>>>(h, wg, nullptr, nullptr, f1, Mrows, DFFf, Cc);
    tgemm<0><<<dim3(DFFf / TBN, Mrows / TBM), 256>>>(h, wu, nullptr, nullptr, f2, Mrows, DFFf, Cc);
    silumul_kernel<<<((int)((size_t)Mrows * DFFf / 4) + 255) / 256, 256>>>(f1, f2, Mrows * (DFFf / 4));
    // 8) out = f1 @ ffn_down_w^T + x1
    tgemm<2><<<dim3(Cc / TBN, Mrows / TBM), 256>>>(f1, wd, nullptr, x1, out, Mrows, Cc, DFFf);
}

// round 5
// speedup vs baseline: 3.0586x; 1.0046x over previous
#include <cuda_runtime.h>
#include <math.h>

#define Bb   2
#define Tt   2048
#define Cc   1024
#define Hh   16
#define DHd  64
#define WINw 256
#define Kk   32
#define DFFf 4096
#define Mrows (Bb*Tt)   // 4096

// ---------------- scratch ----------------
__device__ float g_h   [Mrows*Cc];
__device__ float g_qkv [Mrows*3*Cc];
__device__ float g_ao  [Mrows*Cc];
__device__ float g_proj[Mrows*Cc];
__device__ float g_u   [Mrows*Kk];
__device__ float g_y   [Mrows*Kk];
__device__ float g_tg  [Mrows*Kk];
__device__ float g_trn [Mrows*Cc];
__device__ float g_gate[Mrows];
__device__ float g_x1  [Mrows*Cc];
__device__ float g_f1  [(size_t)Mrows*DFFf];
// tf32-rounded weight copies
__device__ float g_wq [3*Cc*Cc];
__device__ float g_wp [Cc*Cc];
__device__ float g_wg [(size_t)DFFf*Cc];
__device__ float g_wu [(size_t)DFFf*Cc];
__device__ float g_wd [(size_t)Cc*DFFf];

__device__ __forceinline__ unsigned f2tf(float f) {
    unsigned r;
    asm("cvt.rna.tf32.f32 %0, %1;" : "=r"(r) : "f"(f));
    return r;
}
__device__ __forceinline__ float tf32r(float f) {
    return __uint_as_float(f2tf(f));
}

// ---------------- weight tf32 pre-round ----------------
__global__ void round_tf32_kernel(const float* __restrict__ in, float* __restrict__ out, int n4) {
    int idx = blockIdx.x * blockDim.x + threadIdx.x;
    if (idx >= n4) return;
    float4 v = ((const float4*)in)[idx];
    v.x = tf32r(v.x); v.y = tf32r(v.y); v.z = tf32r(v.z); v.w = tf32r(v.w);
    ((float4*)out)[idx] = v;
}

// ---------------- RMSNorm (tf32-rounded output) ----------------
__global__ void rms_kernel(const float* __restrict__ x, const float* __restrict__ w,
                           float* __restrict__ o) {
    int row = blockIdx.x;
    int tid = threadIdx.x;
    const float4* xr = (const float4*)(x + (size_t)row * Cc);
    float4 v = xr[tid];
    float s = v.x*v.x + v.y*v.y + v.z*v.z + v.w*v.w;
    __shared__ float red[8];
    int lane = tid & 31, warp = tid >> 5;
    #pragma unroll
    for (int o2 = 16; o2; o2 >>= 1) s += __shfl_xor_sync(0xffffffffu, s, o2);
    if (lane == 0) red[warp] = s;
    __syncthreads();
    if (warp == 0) {
        float t = (lane < 8) ? red[lane] : 0.f;
        #pragma unroll
        for (int o2 = 4; o2; o2 >>= 1) t += __shfl_xor_sync(0xffffffffu, t, o2);
        if (lane == 0) red[0] = t;
    }
    __syncthreads();
    float inv = rsqrtf(red[0] * (1.0f / Cc) + 1e-6f);
    float4 wv = ((const float4*)w)[tid];
    float4 ov = make_float4(tf32r(v.x*inv*wv.x), tf32r(v.y*inv*wv.y),
                            tf32r(v.z*inv*wv.z), tf32r(v.w*inv*wv.w));
    ((float4*)(o + (size_t)row * Cc))[tid] = ov;
}

// ---------------- fused mix + RMSNorm: x1 = x + g*ao + (1-g)*trn; h = rms(x1)*w [tf32] ----------------
__global__ void mix_rms_kernel(const float* __restrict__ x, const float* __restrict__ ap,
                               const float* __restrict__ trn, const float* __restrict__ g,
                               const float* __restrict__ w,
                               float* __restrict__ x1, float* __restrict__ h) {
    int row = blockIdx.x;
    int tid = threadIdx.x;
    size_t off = (size_t)row * Cc / 4 + tid;
    float gg = g[row];
    float og = 1.f - gg;
    float4 xv = ((const float4*)x)[off];
    float4 av = ((const float4*)ap)[off];
    float4 tv = ((const float4*)trn)[off];
    float4 v = make_float4(xv.x + gg*av.x + og*tv.x,
                           xv.y + gg*av.y + og*tv.y,
                           xv.z + gg*av.z + og*tv.z,
                           xv.w + gg*av.w + og*tv.w);
    ((float4*)x1)[off] = v;
    float s = v.x*v.x + v.y*v.y + v.z*v.z + v.w*v.w;
    __shared__ float red[8];
    int lane = tid & 31, warp = tid >> 5;
    #pragma unroll
    for (int o2 = 16; o2; o2 >>= 1) s += __shfl_xor_sync(0xffffffffu, s, o2);
    if (lane == 0) red[warp] = s;
    __syncthreads();
    if (warp == 0) {
        float t = (lane < 8) ? red[lane] : 0.f;
        #pragma unroll
        for (int o2 = 4; o2; o2 >>= 1) t += __shfl_xor_sync(0xffffffffu, t, o2);
        if (lane == 0) red[0] = t;
    }
    __syncthreads();
    float inv = rsqrtf(red[0] * (1.0f / Cc) + 1e-6f);
    float4 wv = ((const float4*)w)[tid];
    float4 ov = make_float4(tf32r(v.x*inv*wv.x), tf32r(v.y*inv*wv.y),
                            tf32r(v.z*inv*wv.z), tf32r(v.w*inv*wv.w));
    ((float4*)h)[off] = ov;
}

// ---------------- TF32 tensor-core GEMM ----------------
#define TBM 128
#define TBN 128
#define TBK 32
#define TLDK 36

__device__ __forceinline__ void cp_async16(unsigned sa, const float* gp) {
    asm volatile("cp.async.cg.shared.global [%0], [%1], 16;" :: "r"(sa), "l"(gp));
}
__device__ __forceinline__ void cp_commit() {
    asm volatile("cp.async.commit_group;");
}
template<int N>
__device__ __forceinline__ void cp_wait() {
    asm volatile("cp.async.wait_group %0;" :: "n"(N));
}
__device__ __forceinline__ void mma_tf32(float* d, const unsigned* a, const unsigned* b) {
    asm volatile(
        "mma.sync.aligned.m16n8k8.row.col.f32.tf32.tf32.f32 "
        "{%0,%1,%2,%3}, {%4,%5,%6,%7}, {%8,%9}, {%0,%1,%2,%3};"
        : "+f"(d[0]), "+f"(d[1]), "+f"(d[2]), "+f"(d[3])
        : "r"(a[0]), "r"(a[1]), "r"(a[2]), "r"(a[3]), "r"(b[0]), "r"(b[1]));
}

// EPI: 0 none, 1 +bias, 2 +res, 3 silu(res)*acc -> tf32 (res==C, in-place f1)
template<int EPI>
__global__ void __launch_bounds__(256, 2)
tgemm(const float* __restrict__ A, const float* __restrict__ W,
      const float* __restrict__ bias, const float* __restrict__ res,
      float* __restrict__ C, int M, int N, int Kd) {
    __shared__ float As[2][TBM][TLDK];
    __shared__ float Ws[2][TBN][TLDK];
    int tid = threadIdx.x;
    int lane = tid & 31, wid = tid >> 5;
    int g = lane >> 2, t = lane & 3;
    int wm = wid & 3, wn = wid >> 2;
    int bm = blockIdx.y, bn = blockIdx.x;
    const float* Ap = A + (size_t)(bm * TBM) * Kd;
    const float* Wp = W + (size_t)(bn * TBN) * Kd;
    int lr = tid >> 3;
    int lc = (tid & 7) * 4;

    unsigned sa_a[2][4], sa_w[2][4];
    #pragma unroll
    for (int bf = 0; bf < 2; bf++)
        #pragma unroll
        for (int i = 0; i < 4; i++) {
            sa_a[bf][i] = (unsigned)__cvta_generic_to_shared(&As[bf][lr + i*32][lc]);
            sa_w[bf][i] = (unsigned)__cvta_generic_to_shared(&Ws[bf][lr + i*32][lc]);
        }

    int niter = Kd / TBK;
    #pragma unroll
    for (int i = 0; i < 4; i++) {
        cp_async16(sa_a[0][i], Ap + (size_t)(lr + i*32) * Kd + lc);
        cp_async16(sa_w[0][i], Wp + (size_t)(lr + i*32) * Kd + lc);
    }
    cp_commit();
    if (niter > 1) {
        #pragma unroll
        for (int i = 0; i < 4; i++) {
            cp_async16(sa_a[1][i], Ap + (size_t)(lr + i*32) * Kd + TBK + lc);
            cp_async16(sa_w[1][i], Wp + (size_t)(lr + i*32) * Kd + TBK + lc);
        }
        cp_commit();
    }

    float acc[2][8][4];
    #pragma unroll
    for (int mi = 0; mi < 2; mi++)
        #pragma unroll
        for (int ni = 0; ni < 8; ni++)
            #pragma unroll
            for (int j = 0; j < 4; j++) acc[mi][ni][j] = 0.f;

    int am0 = wm*32 + g, an0 = wn*64 + g;

    for (int it = 0; it < niter; it++) {
        if (it + 1 < niter) cp_wait<1>(); else cp_wait<0>();
        __syncthreads();
        int buf = it & 1;

        // fragment double-buffer: preload kstep 0
        unsigned afr[2][2][4];
        unsigned bfr[2][8][2];
        #pragma unroll
        for (int mi = 0; mi < 2; mi++) {
            int m = am0 + mi*16;
            afr[0][mi][0] = __float_as_uint(As[buf][m    ][t]);
            afr[0][mi][1] = __float_as_uint(As[buf][m + 8][t]);
            afr[0][mi][2] = __float_as_uint(As[buf][m    ][t + 4]);
            afr[0][mi][3] = __float_as_uint(As[buf][m + 8][t + 4]);
        }
        #pragma unroll
        for (int ni = 0; ni < 8; ni++) {
            int n = an0 + ni*8;
            bfr[0][ni][0] = __float_as_uint(Ws[buf][n][t]);
            bfr[0][ni][1] = __float_as_uint(Ws[buf][n][t + 4]);
        }

        #pragma unroll
        for (int ks = 0; ks < 4; ks++) {
            int cb = ks & 1, nb = cb ^ 1;
            if (ks < 3) {
                int k0 = (ks + 1) * 8;
                #pragma unroll
                for (int mi = 0; mi < 2; mi++) {
                    int m = am0 + mi*16;
                    afr[nb][mi][0] = __float_as_uint(As[buf][m    ][k0 + t]);
                    afr[nb][mi][1] = __float_as_uint(As[buf][m + 8][k0 + t]);
                    afr[nb][mi][2] = __float_as_uint(As[buf][m    ][k0 + t + 4]);
                    afr[nb][mi][3] = __float_as_uint(As[buf][m + 8][k0 + t + 4]);
                }
                #pragma unroll
                for (int ni = 0; ni < 8; ni++) {
                    int n = an0 + ni*8;
                    bfr[nb][ni][0] = __float_as_uint(Ws[buf][n][k0 + t]);
                    bfr[nb][ni][1] = __float_as_uint(Ws[buf][n][k0 + t + 4]);
                }
            }
            #pragma unroll
            for (int mi = 0; mi < 2; mi++)
                #pragma unroll
                for (int ni = 0; ni < 8; ni++)
                    mma_tf32(acc[mi][ni], afr[cb][mi], bfr[cb][ni]);
        }
        __syncthreads();
        if (it + 2 < niter) {
            int k0 = (it + 2) * TBK;
            #pragma unroll
            for (int i = 0; i < 4; i++) {
                cp_async16(sa_a[buf][i], Ap + (size_t)(lr + i*32) * Kd + k0 + lc);
                cp_async16(sa_w[buf][i], Wp + (size_t)(lr + i*32) * Kd + k0 + lc);
            }
            cp_commit();
        }
    }

    #pragma unroll
    for (int mi = 0; mi < 2; mi++) {
        #pragma unroll
        for (int ni = 0; ni < 8; ni++) {
            int row = bm*TBM + wm*32 + mi*16 + g;
            int col = bn*TBN + wn*64 + ni*8 + 2*t;
            float v0 = acc[mi][ni][0], v1 = acc[mi][ni][1];
            float v2 = acc[mi][ni][2], v3 = acc[mi][ni][3];
            if (EPI == 1) {
                float b0 = bias[col], b1 = bias[col + 1];
                v0 += b0; v1 += b1; v2 += b0; v3 += b1;
            }
            if (EPI == 2) {
                const float* r0 = res + (size_t)row * N + col;
                const float* r1 = res + (size_t)(row + 8) * N + col;
                v0 += r0[0]; v1 += r0[1]; v2 += r1[0]; v3 += r1[1];
            }
            if (EPI == 3) {
                const float* r0 = res + (size_t)row * N + col;
                const float* r1 = res + (size_t)(row + 8) * N + col;
                float s0 = r0[0], s1 = r0[1], s2 = r1[0], s3 = r1[1];
                v0 = tf32r(s0 / (1.f + __expf(-s0)) * v0);
                v1 = tf32r(s1 / (1.f + __expf(-s1)) * v1);
                v2 = tf32r(s2 / (1.f + __expf(-s2)) * v2);
                v3 = tf32r(s3 / (1.f + __expf(-s3)) * v3);
            }
            *(float2*)&C[(size_t)row * N + col]       = make_float2(v0, v1);
            *(float2*)&C[(size_t)(row + 8) * N + col] = make_float2(v2, v3);
        }
    }
}

// ---------------- tiled windowed attention (output tf32-rounded) ----------------
#define QT 64
#define NJ 384
#define PSL 388
#define ATTN_SMEM ((64*68*2 + 64*PSL + 64) * 4)

__global__ void attn_tiled(const float* __restrict__ qkv, float* __restrict__ ao) {
    extern __shared__ float sm[];
    float* Qs   = sm;
    float* KVs  = Qs + 64*68;
    float* Ps   = KVs + 64*68;
    float* rsum = Ps + 64*PSL;

    int q0 = blockIdx.x * QT;
    int h = blockIdx.y, b = blockIdx.z;
    int tid = threadIdx.x;
    const size_t rs = 3 * Cc;
    const float* qbase = qkv + (size_t)b * Tt * rs + h * DHd;

    for (int i = tid; i < 64*16; i += 256) {
        int r = i >> 4, c4 = (i & 15) * 4;
        *(float4*)&Qs[r*68 + c4] =
            *(const float4*)(qbase + (size_t)(q0 + r) * rs + c4);
    }
    int kbase = q0 - 256;
    int tx = tid & 15, ty = tid >> 4;

    for (int cc = 0; cc < 6; cc++) {
        for (int i = tid; i < 64*16; i += 256) {
            int r = i >> 4, c4 = (i & 15) * 4;
            int kg = kbase + cc*64 + r;
            float4 v = make_float4(0.f, 0.f, 0.f, 0.f);
            if (kg >= 0 && kg < Tt)
                v = *(const float4*)(qbase + Cc + (size_t)kg * rs + c4);
            *(float4*)&KVs[r*68 + c4] = v;
        }
        __syncthreads();

        float acc[4][4] = {};
        #pragma unroll 4
        for (int d = 0; d < 64; d += 4) {
            float4 qv[4], kv[4];
            #pragma unroll
            for (int r = 0; r < 4; r++) qv[r] = *(float4*)&Qs[(ty*4+r)*68 + d];
            #pragma unroll
            for (int c = 0; c < 4; c++) kv[c] = *(float4*)&KVs[(tx*4+c)*68 + d];
            #pragma unroll
            for (int r = 0; r < 4; r++)
                #pragma unroll
                for (int c = 0; c < 4; c++)
                    acc[r][c] += qv[r].x*kv[c].x + qv[r].y*kv[c].y
                               + qv[r].z*kv[c].z + qv[r].w*kv[c].w;
        }
        #pragma unroll
        for (int r = 0; r < 4; r++) {
            int qi = ty*4 + r;
            #pragma unroll
            for (int c = 0; c < 4; c++) {
                int j = cc*64 + tx*4 + c;
                int kg = kbase + j;
                bool valid = (j >= qi + 1) && (j <= qi + 256) && (kg >= 0);
                Ps[qi*PSL + j] = valid ? acc[r][c] * 0.125f : -1e30f;
            }
        }
        __syncthreads();
    }

    int lane = tid & 31, wrp = tid >> 5;
    for (int q = wrp; q < 64; q += 8) {
        float m = -INFINITY;
        for (int j = lane; j < NJ; j += 32) m = fmaxf(m, Ps[q*PSL + j]);
        #pragma unroll
        for (int o2 = 16; o2; o2 >>= 1) m = fmaxf(m, __shfl_xor_sync(0xffffffffu, m, o2));
        float s = 0.f;
        for (int j = lane; j < NJ; j += 32) {
            float e = __expf(Ps[q*PSL + j] - m);
            Ps[q*PSL + j] = e;
            s += e;
        }
        #pragma unroll
        for (int o2 = 16; o2; o2 >>= 1) s += __shfl_xor_sync(0xffffffffu, s, o2);
        if (lane == 0) rsum[q] = 1.0f / s;
    }
    __syncthreads();

    float4 o0 = make_float4(0,0,0,0), o1 = o0, o2v = o0, o3 = o0;
    for (int cc = 0; cc < 6; cc++) {
        for (int i = tid; i < 64*16; i += 256) {
            int r = i >> 4, c4 = (i & 15) * 4;
            int kg = kbase + cc*64 + r;
            float4 v = make_float4(0.f, 0.f, 0.f, 0.f);
            if (kg >= 0 && kg < Tt)
                v = *(const float4*)(qbase + 2*Cc + (size_t)kg * rs + c4);
            *(float4*)&KVs[r*68 + c4] = v;
        }
        __syncthreads();
        #pragma unroll 4
        for (int jj = 0; jj < 64; jj++) {
            int j = cc*64 + jj;
            float4 vv = *(float4*)&KVs[jj*68 + tx*4];
            float p0 = Ps[(ty*4+0)*PSL + j];
            float p1 = Ps[(ty*4+1)*PSL + j];
            float p2 = Ps[(ty*4+2)*PSL + j];
            float p3 = Ps[(ty*4+3)*PSL + j];
            o0.x += p0*vv.x; o0.y += p0*vv.y; o0.z += p0*vv.z; o0.w += p0*vv.w;
            o1.x += p1*vv.x; o1.y += p1*vv.y; o1.z += p1*vv.z; o1.w += p1*vv.w;
            o2v.x += p2*vv.x; o2v.y += p2*vv.y; o2v.z += p2*vv.z; o2v.w += p2*vv.w;
            o3.x += p3*vv.x; o3.y += p3*vv.y; o3.z += p3*vv.z; o3.w += p3*vv.w;
        }
        __syncthreads();
    }
    {
        float4 outs[4] = {o0, o1, o2v, o3};
        #pragma unroll
        for (int r = 0; r < 4; r++) {
            int q = ty*4 + r;
            float inv = rsum[q];
            float4 ov = outs[r];
            ov.x = tf32r(ov.x * inv); ov.y = tf32r(ov.y * inv);
            ov.z = tf32r(ov.z * inv); ov.w = tf32r(ov.w * inv);
            *(float4*)(ao + (size_t)(b*Tt + q0 + q)*Cc + h*DHd + tx*4) = ov;
        }
    }
}

// ---------------- skinny GEMM ----------------
__global__ void gemm_skinny(const float* __restrict__ A, const float* __restrict__ W,
                            const float* __restrict__ bias, float* __restrict__ Cmat,
                            int Kd, int do_sigmoid) {
    __shared__ float As[16][64];
    __shared__ float Ws[32][65];
    int tx = threadIdx.x, ty = threadIdx.y;
    int tid = ty * 32 + tx;
    int m0 = blockIdx.x * 16;
    float acc0 = 0.f, acc1 = 0.f;
    for (int k0 = 0; k0 < Kd; k0 += 64) {
        int r = tid >> 4, c4 = (tid & 15) * 4;
        float4 av = *(const float4*)&A[(size_t)(m0 + r) * Kd + k0 + c4];
        *(float4*)&As[r][c4] = av;
        int r2 = tid >> 3, c8 = (tid & 7) * 8;
        float4 w0 = *(const float4*)&W[(size_t)r2 * Kd + k0 + c8];
        float4 w1 = *(const float4*)&W[(size_t)r2 * Kd + k0 + c8 + 4];
        Ws[r2][c8+0]=w0.x; Ws[r2][c8+1]=w0.y; Ws[r2][c8+2]=w0.z; Ws[r2][c8+3]=w0.w;
        Ws[r2][c8+4]=w1.x; Ws[r2][c8+5]=w1.y; Ws[r2][c8+6]=w1.z; Ws[r2][c8+7]=w1.w;
        __syncthreads();
        #pragma unroll
        for (int kk = 0; kk < 64; kk++) {
            float wv = Ws[tx][kk];
            acc0 += As[ty][kk] * wv;
            acc1 += As[ty + 8][kk] * wv;
        }
        __syncthreads();
    }
    float b0 = bias ? bias[tx] : 0.f;
    float v0 = acc0 + b0, v1 = acc1 + b0;
    if (do_sigmoid) {
        v0 = 1.f / (1.f + __expf(-v0));
        v1 = 1.f / (1.f + __expf(-v1));
    }
    Cmat[(size_t)(m0 + ty) * Kk + tx]     = v0;
    Cmat[(size_t)(m0 + ty + 8) * Kk + tx] = v1;
}

// ---------------- chunked parallel oscillator scan ----------------
__global__ void scan_kernel(const float* __restrict__ u, const float* __restrict__ a_logit,
                            const float* __restrict__ theta, float* __restrict__ y) {
    __shared__ float ssr[32][33], ssi[32][33];
    int b = blockIdx.x;
    int tid = threadIdx.x;
    int k = tid & 31, c = tid >> 5;
    float a  = 1.f / (1.f + __expf(-a_logit[k]));
    float ct = cosf(theta[k]), st = sinf(theta[k]);
    const float* up = u + (size_t)b * Tt * Kk + k;
    int t0 = c * 64;

    float sr = 0.f, si = 0.f;
    for (int i = 0; i < 64; i++) {
        float ut = up[(size_t)(t0 + i) * Kk];
        float nsr = a * (ct * sr - st * si) + ut;
        float nsi = a * (st * sr + ct * si);
        sr = nsr; si = nsi;
    }
    ssr[c][k] = sr; ssi[c][k] = si;
    __syncthreads();

    if (tid < 32) {
        int kq = tid;
        float aq = 1.f / (1.f + __expf(-a_logit[kq]));
        float a64 = __powf(aq, 64.f);
        float th = theta[kq];
        float c64 = cosf(64.f * th), s64 = sinf(64.f * th);
        float M00 = a64 * c64, M01 = -a64 * s64;
        float M10 = a64 * s64, M11 =  a64 * c64;
        float cr = 0.f, ci = 0.f;
        for (int cc = 0; cc < 32; cc++) {
            float lr = ssr[cc][kq], li = ssi[cc][kq];
            ssr[cc][kq] = cr; ssi[cc][kq] = ci;
            float nr = M00 * cr + M01 * ci + lr;
            float ni = M10 * cr + M11 * ci + li;
            cr = nr; ci = ni;
        }
    }
    __syncthreads();

    sr = ssr[c][k]; si = ssi[c][k];
    float* yp = y + (size_t)b * Tt * Kk + k;
    for (int i = 0; i < 64; i++) {
        float ut = up[(size_t)(t0 + i) * Kk];
        float nsr = a * (ct * sr - st * si) + ut;
        float nsi = a * (st * sr + ct * si);
        sr = nsr; si = nsi;
        yp[(size_t)(t0 + i) * Kk] = sr;
    }
}

// ---------------- trn_out ----------------
__global__ void trn_out_kernel(const float* __restrict__ tg, const float* __restrict__ y,
                               const float* __restrict__ wout, const float* __restrict__ scale_p,
                               float* __restrict__ out) {
    __shared__ float Zs[16][33];
    __shared__ float Ws[64][33];
    int tx = threadIdx.x, ty = threadIdx.y;
    int tid = ty * 64 + tx;
    int m0 = blockIdx.x * 16, c0 = blockIdx.y * 64;
    for (int i = tid; i < 16 * Kk; i += 256) {
        int r = i >> 5, k = i & 31;
        size_t off = (size_t)(m0 + r) * Kk + k;
        Zs[r][k] = tg[off] * y[off];
    }
    for (int i = tid; i < 64 * Kk; i += 256) {
        int r = i >> 5, k = i & 31;
        Ws[r][k] = wout[(size_t)(c0 + r) * Kk + k];
    }
    __syncthreads();
    float scale = scale_p[0];
    float acc[4] = {0.f, 0.f, 0.f, 0.f};
    #pragma unroll
    for (int k = 0; k < Kk; k++) {
        float wv = Ws[tx][k];
        acc[0] += Zs[ty][k]      * wv;
        acc[1] += Zs[ty + 4][k]  * wv;
        acc[2] += Zs[ty + 8][k]  * wv;
        acc[3] += Zs[ty + 12][k] * wv;
    }
    #pragma unroll
    for (int r = 0; r < 4; r++)
        out[(size_t)(m0 + ty + 4 * r) * Cc + c0 + tx] = acc[r] * scale;
}

// ---------------- scalar gate ----------------
__global__ void gate_kernel(const float* __restrict__ h, const float* __restrict__ gw,
                            const float* __restrict__ gb, float* __restrict__ g) {
    int row = blockIdx.x, tid = threadIdx.x;
    float4 a = ((const float4*)(h + (size_t)row * Cc))[tid];
    float4 w = ((const float4*)gw)[tid];
    float s = a.x*w.x + a.y*w.y + a.z*w.z + a.w*w.w;
    __shared__ float red[8];
    int lane = tid & 31, warp = tid >> 5;
    #pragma unroll
    for (int o2 = 16; o2; o2 >>= 1) s += __shfl_xor_sync(0xffffffffu, s, o2);
    if (lane == 0) red[warp] = s;
    __syncthreads();
    if (tid == 0) {
        float t = 0.f;
        #pragma unroll
        for (int i = 0; i < 8; i++) t += red[i];
        g[row] = 1.f / (1.f + __expf(-(t + gb[0])));
    }
}

// ---------------- launch ----------------
extern "C" void kernel_launch(void* const* d_in, const int* in_sizes, int n_in,
                              void* d_out, int out_size) {
    const float* x          = (const float*)d_in[0];
    const float* norm1_w    = (const float*)d_in[1];
    const float* qkv_w      = (const float*)d_in[2];
    const float* qkv_b      = (const float*)d_in[3];
    const float* proj_w     = (const float*)d_in[4];
    const float* proj_b     = (const float*)d_in[5];
    const float* gate_w     = (const float*)d_in[6];
    const float* gate_b     = (const float*)d_in[7];
    const float* trn_win    = (const float*)d_in[8];
    const float* trn_wout   = (const float*)d_in[9];
    const float* trn_gate_w = (const float*)d_in[10];
    const float* trn_gate_b = (const float*)d_in[11];
    const float* trn_a      = (const float*)d_in[12];
    const float* trn_theta  = (const float*)d_in[13];
    const float* trn_scale  = (const float*)d_in[14];
    const float* norm2_w    = (const float*)d_in[15];
    const float* ffn_gate_w = (const float*)d_in[16];
    const float* ffn_up_w   = (const float*)d_in[17];
    const float* ffn_down_w = (const float*)d_in[18];
    float* out = (float*)d_out;

    float *h, *qkv, *ao, *proj, *u, *y, *tg, *trn, *gate, *x1, *f1;
    float *wq, *wp, *wg, *wu, *wd;
    cudaGetSymbolAddress((void**)&h,    g_h);
    cudaGetSymbolAddress((void**)&qkv,  g_qkv);
    cudaGetSymbolAddress((void**)&ao,   g_ao);
    cudaGetSymbolAddress((void**)&proj, g_proj);
    cudaGetSymbolAddress((void**)&u,    g_u);
    cudaGetSymbolAddress((void**)&y,    g_y);
    cudaGetSymbolAddress((void**)&tg,   g_tg);
    cudaGetSymbolAddress((void**)&trn,  g_trn);
    cudaGetSymbolAddress((void**)&gate, g_gate);
    cudaGetSymbolAddress((void**)&x1,   g_x1);
    cudaGetSymbolAddress((void**)&f1,   g_f1);
    cudaGetSymbolAddress((void**)&wq,   g_wq);
    cudaGetSymbolAddress((void**)&wp,   g_wp);
    cudaGetSymbolAddress((void**)&wg,   g_wg);
    cudaGetSymbolAddress((void**)&wu,   g_wu);
    cudaGetSymbolAddress((void**)&wd,   g_wd);

    cudaFuncSetAttribute(attn_tiled, cudaFuncAttributeMaxDynamicSharedMemorySize, ATTN_SMEM);

    // 0) pre-round weights to tf32
    {
        int n4q = 3*Cc*Cc/4, n4p = Cc*Cc/4, n4f = DFFf*Cc/4;
        round_tf32_kernel<<<(n4q+255)/256, 256>>>(qkv_w, wq, n4q);
        round_tf32_kernel<<<(n4p+255)/256, 256>>>(proj_w, wp, n4p);
        round_tf32_kernel<<<(n4f+255)/256, 256>>>(ffn_gate_w, wg, n4f);
        round_tf32_kernel<<<(n4f+255)/256, 256>>>(ffn_up_w,   wu, n4f);
        round_tf32_kernel<<<(n4f+255)/256, 256>>>(ffn_down_w, wd, n4f);
    }

    // 1) h = rms(x, norm1_w)
    rms_kernel<<<Mrows, 256>>>(x, norm1_w, h);
    // 2) qkv
    tgemm<1><<<dim3(3 * Cc / TBN, Mrows / TBM), 256>>>(h, wq, qkv_b, nullptr, qkv, Mrows, 3 * Cc, Cc);
    // 3) attention
    attn_tiled<<<dim3(Tt / QT, Hh, Bb), 256, ATTN_SMEM>>>(qkv, ao);
    // 4) proj
    tgemm<1><<<dim3(Cc / TBN, Mrows / TBM), 256>>>(ao, wp, proj_b, nullptr, proj, Mrows, Cc, Cc);
    // 5) TRN branch
    gemm_skinny<<<Mrows / 16, dim3(32, 8)>>>(h, trn_win, nullptr, u, Cc, 0);
    gemm_skinny<<<Mrows / 16, dim3(32, 8)>>>(h, trn_gate_w, trn_gate_b, tg, Cc, 1);
    scan_kernel<<<Bb, 1024>>>(u, trn_a, trn_theta, y);
    trn_out_kernel<<<dim3(Mrows / 16, Cc / 64), dim3(64, 4)>>>(tg, y, trn_wout, trn_scale, trn);
    // 6) gate + fused mix+rms2 (writes x1 and h)
    gate_kernel<<<Mrows, 256>>>(h, gate_w, gate_b, gate);
    mix_rms_kernel<<<Mrows, 256>>>(x, proj, trn, gate, norm2_w, x1, h);
    // 7) FFN: f1 = h@Wg^T ; then f1 = tf32(silu(f1) * (h@Wu^T)) fused in epilogue
    tgemm<0><<<dim3(DFFf / TBN, Mrows / TBM), 256>>>(h, wg, nullptr, nullptr, f1, Mrows, DFFf, Cc);
    tgemm<3><<<dim3(DFFf / TBN, Mrows / TBM), 256>>>(h, wu, nullptr, f1, f1, Mrows, DFFf, Cc);
    // 8) out = f1 @ Wd^T + x1
    tgemm<2><<<dim3(Cc / TBN, Mrows / TBM), 256>>>(f1, wd, nullptr, x1, out, Mrows, Cc, DFFf);
}